// round 10
// baseline (speedup 1.0000x reference)
#include <cuda_runtime.h>
#include <cuda_fp16.h>
#include <stdint.h>

#define NROWS 8192
#define INP   512
#define NOUT  128
#define SLOPE 0.2f

// ---------------- device scratch ----------------
__device__ float  g_f1[NROWS];
__device__ float  g_f2[NROWS];
__device__ float  g_A[NROWS];
__device__ float  g_C[NROWS];
__device__ unsigned int g_bits[NROWS * 256];    // 8 MB bitpacked adj
__device__ uint4  g_UVT2[2 * 128 * 1024];       // 4 MB: {U,V} fp16 pre-swizzled B^T tiles
__device__ uint4  g_ZT[128 * 64];               // per chunk: 8 rows x 64 j fp16 (u, v, zero...)
__device__ float  g_pp[2 * NROWS * NOUT];
__device__ float  g_pn[2 * NROWS * NOUT];
__device__ float  g_zu[2 * NROWS];
__device__ float  g_zv[2 * NROWS];
__device__ unsigned int g_cnt;

// ---------------- helpers ----------------
__device__ __forceinline__ uint32_t smem_u32(const void* p) {
    uint32_t r;
    asm("{ .reg .u64 t; cvta.to.shared.u64 t, %1; cvt.u32.u64 %0, t; }" : "=r"(r) : "l"(p));
    return r;
}
#define SW128(x) ((x) ^ (((x) >> 3) & 0x70))

#define LDSM_X4(r0, r1, r2, r3, addr) \
    asm volatile("ldmatrix.sync.aligned.m8n8.x4.shared.b16 {%0,%1,%2,%3}, [%4];" \
        : "=r"(r0), "=r"(r1), "=r"(r2), "=r"(r3) : "r"(addr))

#define MMA16816(d, a0, a1, a2, a3, b0, b1) \
    asm volatile("mma.sync.aligned.m16n8k16.row.col.f32.f16.f16.f32 " \
        "{%0,%1,%2,%3},{%4,%5,%6,%7},{%8,%9},{%0,%1,%2,%3};" \
        : "+f"((d)[0]), "+f"((d)[1]), "+f"((d)[2]), "+f"((d)[3]) \
        : "r"(a0), "r"(a1), "r"(a2), "r"(a3), "r"(b0), "r"(b1))

__device__ __forceinline__ void cp_async16(uint32_t dst, const void* src) {
    asm volatile("cp.async.cg.shared.global [%0], [%1], 16;" :: "r"(dst), "l"(src) : "memory");
}
__device__ __forceinline__ void cp_async8(uint32_t dst, const void* src) {
    asm volatile("cp.async.ca.shared.global [%0], [%1], 8;" :: "r"(dst), "l"(src) : "memory");
}
#define CP_COMMIT() asm volatile("cp.async.commit_group;" ::: "memory")
#define CP_WAIT1()  asm volatile("cp.async.wait_group 1;" ::: "memory")

__device__ __forceinline__ unsigned pack_f16x2(float lo, float hi) {
    unsigned r;
    asm("cvt.rn.f16x2.f32 %0, %1, %2;" : "=r"(r) : "f"(hi), "f"(lo));
    return r;
}
__device__ __forceinline__ unsigned prmt(unsigned a, unsigned b, unsigned s) {
    unsigned r;
    asm("prmt.b32 %0, %1, %2, %3;" : "=r"(r) : "r"(a), "r"(b), "r"(s));
    return r;
}

// ============ kA: fused [Wh GEMM + features + UVT/ZT] + [interleaved adj bitpack] ============
// 128 CTAs x 256 threads. CTA b: GEMM rows b*64..b*64+63 AND packs the SAME 64 adj rows,
// 1/16th per GEMM k-step (pack DRAM hides under the FFMA wall).
__global__ __launch_bounds__(256, 1) void kA(const float* __restrict__ h, const float* __restrict__ W,
                                             const float* __restrict__ a, const int* __restrict__ adj) {
    __shared__ float hs[64][33];
    __shared__ float Ws[32][128];
    const int t  = threadIdx.x;
    const int i0 = blockIdx.x * 64;
    const int tx = t & 31;
    const int ty = t >> 5;

    // pack assignment: thread t owns row i0+(t>>2), words (t&3)*64 .. +63 (8KB contiguous adj)
    const char* pack_src = (const char*)adj
        + ((size_t)(i0 + (t >> 2)) * NROWS + (size_t)(t & 3) * 2048) * 4;
    unsigned* pack_dst = g_bits + (size_t)(i0 + (t >> 2)) * 256 + (t & 3) * 64;

    float acc[8][4];
#pragma unroll
    for (int r = 0; r < 8; r++)
#pragma unroll
        for (int c = 0; c < 4; c++) acc[r][c] = 0.f;

    for (int k0 = 0; k0 < INP; k0 += 32) {
        const int s = k0 >> 5;   // slice 0..15
#pragma unroll
        for (int p = 0; p < 2; p++) {
            int u = t + p * 256;
            int r = u >> 3, kc = (u & 7) * 4;
            float4 hv = *(const float4*)(h + (size_t)(i0 + r) * INP + k0 + kc);
            hs[r][kc] = hv.x; hs[r][kc + 1] = hv.y; hs[r][kc + 2] = hv.z; hs[r][kc + 3] = hv.w;
        }
#pragma unroll
        for (int p = 0; p < 4; p++) {
            int u = t + p * 256;
            int kr = u >> 5, cc = (u & 31) * 4;
            *(float4*)&Ws[kr][cc] = *(const float4*)(W + (size_t)(k0 + kr) * NOUT + cc);
        }

        // ---- pack slice s: 4 words (512B of adj) per thread ----
        {
            const char* ps = pack_src + s * 512;
#pragma unroll 2
            for (int q = 0; q < 4; q++) {
                int4 v[8];
#pragma unroll
                for (int k = 0; k < 8; k++)
                    v[k] = __ldg((const int4*)(ps + q * 128 + k * 16));
                unsigned w = 0;
#pragma unroll
                for (int k = 0; k < 8; k++) {
                    w += (unsigned)v[k].x << (k * 4 + 0);
                    w += (unsigned)v[k].y << (k * 4 + 1);
                    w += (unsigned)v[k].z << (k * 4 + 2);
                    w += (unsigned)v[k].w << (k * 4 + 3);
                }
                pack_dst[s * 4 + q] = w;
            }
        }

        __syncthreads();
#pragma unroll
        for (int kk = 0; kk < 32; kk++) {
            float4 bv = *(float4*)&Ws[kk][tx * 4];
#pragma unroll
            for (int r = 0; r < 8; r++) {
                float av = hs[ty * 8 + r][kk];
                acc[r][0] += av * bv.x; acc[r][1] += av * bv.y;
                acc[r][2] += av * bv.z; acc[r][3] += av * bv.w;
            }
        }
        __syncthreads();
    }

    float4 a1 = __ldg((const float4*)(a + tx * 4));
    float4 a2 = __ldg((const float4*)(a + 128 + tx * 4));
    float uu[8], vv[8];
#pragma unroll
    for (int r = 0; r < 8; r++) {
        float s1 = acc[r][0] * a1.x + acc[r][1] * a1.y + acc[r][2] * a1.z + acc[r][3] * a1.w;
        float s2 = acc[r][0] * a2.x + acc[r][1] * a2.y + acc[r][2] * a2.z + acc[r][3] * a2.w;
#pragma unroll
        for (int off = 16; off > 0; off >>= 1) {
            s1 += __shfl_xor_sync(0xffffffffu, s1, off);
            s2 += __shfl_xor_sync(0xffffffffu, s2, off);
        }
        uu[r] = expf(s2);
        vv[r] = expf(SLOPE * s2);
        if (tx == r) {
            int j = i0 + ty * 8 + r;
            g_f1[j] = s1;
            g_f2[j] = s2;
            g_A[j]  = expf(s1);
            g_C[j]  = expf(SLOPE * s1);
        }
    }

    const int jbase = ty * 8;
    char* base = (char*)g_UVT2 + (size_t)blockIdx.x * 16384;
#pragma unroll
    for (int rp = 0; rp < 4; rp++) {
#pragma unroll
        for (int c = 0; c < 4; c++) {
            float U0 = uu[2 * rp] * acc[2 * rp][c],     U1 = uu[2 * rp + 1] * acc[2 * rp + 1][c];
            float V0 = vv[2 * rp] * acc[2 * rp][c],     V1 = vv[2 * rp + 1] * acc[2 * rp + 1][c];
            unsigned off = SW128((unsigned)((tx * 4 + c) * 128 + (jbase + 2 * rp) * 2));
            *(unsigned*)(base + off)            = pack_f16x2(U0, U1);
            *(unsigned*)(base + 2097152u + off) = pack_f16x2(V0, V1);
        }
    }

    {
        char* zb = (char*)g_ZT + (size_t)blockIdx.x * 1024;
        int rsel = tx & 7;
        float us = uu[0], vs = vv[0];
#pragma unroll
        for (int r = 1; r < 8; r++) if (rsel == r) { us = uu[r]; vs = vv[r]; }
        int n = tx >> 3;
        if (n < 2) {
            float val = (n == 0) ? us : vs;
            unsigned off = (unsigned)(n * 128) + (((unsigned)((jbase + rsel) * 2)) ^ ((unsigned)n << 4));
            *(__half*)(zb + off) = __float2half(val);
        }
        if (t < 192) {
            int zn = 2 + (t >> 5);
            unsigned zoff = (unsigned)(zn * 128) + ((((unsigned)(t & 31)) * 4u) ^ ((unsigned)(zn & 7) << 4));
            *(unsigned*)(zb + zoff) = 0u;
        }
    }
}

// ============ K4: fp16 HMMA masked GEMMs + Z streams + device-wide combine ============
#define MASKBUF   32768
#define BTILE     16384
#define ZTB       1024
#define BBUF      (2 * BTILE + ZTB)              // 33792
#define DYNSMEM   (2 * MASKBUF + 3 * BBUF)       // 166912 (B triple-buffered: no write/read race)

__global__ void __launch_bounds__(512, 1) k4_hmma(float* __restrict__ out) {
    extern __shared__ __align__(16) char dyn[];
    __shared__ float s_f1[128];
    __shared__ __align__(16) float s_f2[4096];
    __shared__ __align__(16) unsigned sbits[3 * 256];

    const int tid  = threadIdx.x;
    const int wid  = tid >> 5;
    const int lane = tid & 31;
    const int rt = blockIdx.x >> 1;
    const int hh = blockIdx.x & 1;
    const int i0 = rt << 7;
    const int j0 = hh << 12;

    const uint32_t dbase  = smem_u32(dyn);
    const uint32_t bbuf_u = dbase + 2u * MASKBUF;
    const uint32_t sbits_u = smem_u32(sbits);

    if (tid < 128) s_f1[tid] = g_f1[i0 + tid];
    for (int q = tid; q < 4096; q += 512) s_f2[q] = g_f2[j0 + q];
    __syncthreads();

    float dp[2][4][4], dn[2][4][4];
    float dzp[2][4], dzn[2][4];
#pragma unroll
    for (int mt = 0; mt < 2; mt++) {
#pragma unroll
        for (int nt = 0; nt < 4; nt++)
#pragma unroll
            for (int r = 0; r < 4; r++) { dp[mt][nt][r] = 0.f; dn[mt][nt][r] = 0.f; }
#pragma unroll
        for (int r = 0; r < 4; r++) { dzp[mt][r] = 0.f; dzn[mt][r] = 0.f; }
    }

    const int warp_m = wid >> 2;
    const int warp_n = wid & 3;
    const bool diag = (warp_m == warp_n);
    const int ib = warp_m << 5;
    const int cb = warp_n << 5;

    const int ri0 = ib + (lane & 15);
    const int ri1 = ri0 + 16;
    const uint32_t arow0 = (uint32_t)ri0 * 128u, asw0 = (uint32_t)(ri0 & 7) << 4;
    const uint32_t arow1 = (uint32_t)ri1 * 128u, asw1 = (uint32_t)(ri1 & 7) << 4;
    const uint32_t akh   = (uint32_t)(lane >> 4) << 4;
    const int cr = cb + lane;
    const uint32_t brow = (uint32_t)cr * 128u, bsw = (uint32_t)(cr & 7) << 4;

    const uint32_t zn   = (uint32_t)(lane >> 2);
    const uint32_t zsw  = (zn & 7u) << 4;
    const uint32_t zrow = 2u * BTILE + zn * 128u;
    const uint32_t zkb  = ((uint32_t)(lane & 3)) << 2;

    auto prefetch_bits = [&](int c) {
        if (tid < 128) {
            uint32_t dst = sbits_u + (uint32_t)(c % 3) * 1024u + (uint32_t)tid * 8u;
            const unsigned* src = &g_bits[(size_t)(i0 + tid) * 256 + (unsigned)((j0 + (c << 6)) >> 5)];
            cp_async8(dst, src);
        }
    };

    auto build_masks = [&](int c, int mb) {
        char* mdst = dyn + mb * MASKBUF;
        const int tch = c << 6;
        const unsigned* sb = sbits + (c % 3) * 256;
#pragma unroll
        for (int un = 0; un < 2; un++) {
            const int unit = (tid << 1) | un;
            const int i  = unit >> 3;
            const int jl = (unit & 7) << 3;
            const unsigned word = sb[i * 2 + (jl >> 5)];
            const unsigned bits8 = (word >> (jl & 31)) & 0xFFu;
            const float thr = -s_f1[i];
            const float4 fA = *(const float4*)&s_f2[tch + jl];
            const float4 fB = *(const float4*)&s_f2[tch + jl + 4];
            const float fs[8] = {fA.x, fA.y, fA.z, fA.w, fB.x, fB.y, fB.z, fB.w};
            unsigned pn[8];
#pragma unroll
            for (int e = 0; e < 8; e++) {
                unsigned sel = (fs[e] >= thr) ? 0x00003C00u : 0x3C000000u;
                pn[e] = ((bits8 >> e) & 1u) * sel;
            }
            uint4 wp4, wn4;
            wp4.x = prmt(pn[0], pn[1], 0x5410u); wn4.x = prmt(pn[0], pn[1], 0x7632u);
            wp4.y = prmt(pn[2], pn[3], 0x5410u); wn4.y = prmt(pn[2], pn[3], 0x7632u);
            wp4.z = prmt(pn[4], pn[5], 0x5410u); wn4.z = prmt(pn[4], pn[5], 0x7632u);
            wp4.w = prmt(pn[6], pn[7], 0x5410u); wn4.w = prmt(pn[6], pn[7], 0x7632u);
            const uint32_t off = (uint32_t)i * 128u + (((uint32_t)(jl << 1)) ^ ((uint32_t)(i & 7) << 4));
            *(uint4*)(mdst + off)          = wp4;
            *(uint4*)(mdst + 16384 + off)  = wn4;
        }
    };

    auto prefetch_B = [&](int c) {
        const int nc = (hh << 6) + c;
        const uint32_t dstb = bbuf_u + (uint32_t)(c % 3) * BBUF;
        const char* srcb = (const char*)g_UVT2 + (size_t)nc * 16384;
#pragma unroll
        for (int pass = 0; pass < 4; pass++) {
            int u = tid + pass * 512;
            int m = u >> 10;
            uint32_t off = (uint32_t)(u & 1023) << 4;
            cp_async16(dstb + (uint32_t)m * BTILE + off, srcb + (size_t)m * 2097152 + off);
        }
        if (tid < 64)
            cp_async16(dstb + 2u * BTILE + (uint32_t)tid * 16u,
                       (const char*)g_ZT + (size_t)nc * 1024 + tid * 16);
    };

    // ---- prologue ----
    prefetch_bits(0);
    prefetch_bits(1);
    prefetch_B(0);
    CP_COMMIT();                 // g1: B0, z0, bits0, bits1
    prefetch_bits(2);
    prefetch_B(1);
    CP_COMMIT();                 // g2: B1, z1, bits2
    CP_WAIT1();                  // g1 complete
    __syncthreads();
    build_masks(0, 0);

    for (int t = 0; t < 64; t++) {
        CP_WAIT1();              // everything except last group complete → B[t], bits[t+2]
        __syncthreads();         // masks[t] visible

        const uint32_t mpos = dbase + (uint32_t)(t & 1) * MASKBUF;
        const uint32_t mneg = mpos + 16384u;
        const uint32_t bufb = bbuf_u + (uint32_t)(t % 3) * BBUF;

#pragma unroll
        for (int ks = 0; ks < 4; ks++) {
            const uint32_t joff = ((uint32_t)ks << 5) | akh;
            uint32_t ap0[4], ap1[4], an0[4], an1[4];
            LDSM_X4(ap0[0], ap0[1], ap0[2], ap0[3], mpos + arow0 + (joff ^ asw0));
            LDSM_X4(ap1[0], ap1[1], ap1[2], ap1[3], mpos + arow1 + (joff ^ asw1));
            LDSM_X4(an0[0], an0[1], an0[2], an0[3], mneg + arow0 + (joff ^ asw0));
            LDSM_X4(an1[0], an1[1], an1[2], an1[3], mneg + arow1 + (joff ^ asw1));

            {
                uint32_t b0[4], b1[4];
                const uint32_t pb = bufb + brow;
                LDSM_X4(b0[0], b0[1], b0[2], b0[3], pb + ((((uint32_t)ks << 5) | 0u)  ^ bsw));
                LDSM_X4(b1[0], b1[1], b1[2], b1[3], pb + ((((uint32_t)ks << 5) | 16u) ^ bsw));
#pragma unroll
                for (int nt = 0; nt < 4; nt++) {
                    MMA16816(dp[0][nt], ap0[0], ap0[1], ap0[2], ap0[3], b0[nt], b1[nt]);
                    MMA16816(dp[1][nt], ap1[0], ap1[1], ap1[2], ap1[3], b0[nt], b1[nt]);
                }
            }
            {
                uint32_t b0[4], b1[4];
                const uint32_t pb = bufb + BTILE + brow;
                LDSM_X4(b0[0], b0[1], b0[2], b0[3], pb + ((((uint32_t)ks << 5) | 0u)  ^ bsw));
                LDSM_X4(b1[0], b1[1], b1[2], b1[3], pb + ((((uint32_t)ks << 5) | 16u) ^ bsw));
#pragma unroll
                for (int nt = 0; nt < 4; nt++) {
                    MMA16816(dn[0][nt], an0[0], an0[1], an0[2], an0[3], b0[nt], b1[nt]);
                    MMA16816(dn[1][nt], an1[0], an1[1], an1[2], an1[3], b0[nt], b1[nt]);
                }
            }
            if (diag) {
                const uint32_t zk = ((uint32_t)ks << 5) + zkb;
                const uint32_t a0 = bufb + zrow + (zk ^ zsw);
                const uint32_t a1 = bufb + zrow + ((zk + 16u) ^ zsw);
                uint32_t bz0, bz1;
                asm volatile("ld.shared.b32 %0, [%1];" : "=r"(bz0) : "r"(a0));
                asm volatile("ld.shared.b32 %0, [%1];" : "=r"(bz1) : "r"(a1));
                MMA16816(dzp[0], ap0[0], ap0[1], ap0[2], ap0[3], bz0, bz1);
                MMA16816(dzp[1], ap1[0], ap1[1], ap1[2], ap1[3], bz0, bz1);
                MMA16816(dzn[0], an0[0], an0[1], an0[2], an0[3], bz0, bz1);
                MMA16816(dzn[1], an1[0], an1[1], an1[2], an1[3], bz0, bz1);
            }
        }

        if (t < 63) build_masks(t + 1, (t + 1) & 1);
        if (t + 2 < 64) {
            prefetch_B(t + 2);           // buffer (t+2)%3: not read until iter t+2, written now — no race
            if (t + 3 < 64) prefetch_bits(t + 3);
        }
        CP_COMMIT();
    }

    // ---- write raw partials ----
    float* pdst = g_pp + (size_t)hh * (NROWS * NOUT);
    float* ndst = g_pn + (size_t)hh * (NROWS * NOUT);
#pragma unroll
    for (int mt = 0; mt < 2; mt++) {
        const int r0 = i0 + ib + mt * 16 + (lane >> 2);
        const int r1 = r0 + 8;
#pragma unroll
        for (int nt = 0; nt < 4; nt++) {
            const int c = cb + nt * 8 + ((lane & 3) << 1);
            *(float2*)&pdst[(size_t)r0 * NOUT + c] = make_float2(dp[mt][nt][0], dp[mt][nt][1]);
            *(float2*)&pdst[(size_t)r1 * NOUT + c] = make_float2(dp[mt][nt][2], dp[mt][nt][3]);
            *(float2*)&ndst[(size_t)r0 * NOUT + c] = make_float2(dn[mt][nt][0], dn[mt][nt][1]);
            *(float2*)&ndst[(size_t)r1 * NOUT + c] = make_float2(dn[mt][nt][2], dn[mt][nt][3]);
        }
    }
    if (diag) {
#pragma unroll
        for (int mt = 0; mt < 2; mt++) {
            const int r0 = i0 + ib + mt * 16 + (lane >> 2);
            if ((lane & 3) == 0) {
                g_zu[hh * NROWS + r0]     = dzp[mt][0];
                g_zu[hh * NROWS + r0 + 8] = dzp[mt][2];
                g_zv[hh * NROWS + r0]     = dzn[mt][1];
                g_zv[hh * NROWS + r0 + 8] = dzn[mt][3];
            }
        }
    }

    // ---- device-wide barrier ----
    __threadfence();
    __syncthreads();
    if (tid == 0) {
        unsigned t0 = atomicAdd(&g_cnt, 1u);
        unsigned target = ((t0 >> 7) + 1u) << 7;
        unsigned cur;
        do {
            asm volatile("ld.acquire.gpu.u32 %0, [%1];" : "=r"(cur) : "l"(&g_cnt));
            if (cur < target) __nanosleep(128);
        } while (cur < target);
    }
    __syncthreads();

    // ---- combine ----
    {
        const int rbase = blockIdx.x * 64;
#pragma unroll
        for (int it = 0; it < 4; it++) {
            int u = tid + it * 512;
            int r = rbase + (u >> 5);
            int c = (u & 31) * 4;
            float A = g_A[r], Cc = g_C[r];
            float z = A * (g_zu[r] + g_zu[NROWS + r]) + Cc * (g_zv[r] + g_zv[NROWS + r]);
            float zi = 1.f / z;
            const float4 p0 = *(const float4*)&g_pp[(size_t)r * NOUT + c];
            const float4 p1 = *(const float4*)&g_pp[(size_t)(NROWS + r) * NOUT + c];
            const float4 n0 = *(const float4*)&g_pn[(size_t)r * NOUT + c];
            const float4 n1 = *(const float4*)&g_pn[(size_t)(NROWS + r) * NOUT + c];
            float4 o;
            o.x = (A * (p0.x + p1.x) + Cc * (n0.x + n1.x)) * zi;
            o.y = (A * (p0.y + p1.y) + Cc * (n0.y + n1.y)) * zi;
            o.z = (A * (p0.z + p1.z) + Cc * (n0.z + n1.z)) * zi;
            o.w = (A * (p0.w + p1.w) + Cc * (n0.w + n1.w)) * zi;
            *(float4*)&out[(size_t)r * NOUT + c] = o;
        }
    }
}

// ---------------- launcher ----------------
extern "C" void kernel_launch(void* const* d_in, const int* in_sizes, int n_in,
                              void* d_out, int out_size) {
    const float* h = nullptr; const int* adj = nullptr; const float* W = nullptr; const float* a = nullptr;
    for (int k = 0; k < n_in; k++) {
        switch (in_sizes[k]) {
            case NROWS * INP:   h   = (const float*)d_in[k]; break;
            case NROWS * NROWS: adj = (const int*)d_in[k];   break;
            case INP * NOUT:    W   = (const float*)d_in[k]; break;
            case 2 * NOUT:      a   = (const float*)d_in[k]; break;
            default: break;
        }
    }
    float* out = (float*)d_out;

    cudaFuncSetAttribute(k4_hmma, cudaFuncAttributeMaxDynamicSharedMemorySize, DYNSMEM);

    kA     <<<128, 256>>>(h, W, a, adj);
    k4_hmma<<<128, 512, DYNSMEM>>>(out);
}

// round 11
// speedup vs baseline: 1.0886x; 1.0886x over previous
#include <cuda_runtime.h>
#include <cuda_fp16.h>
#include <stdint.h>

#define NROWS 8192
#define INP   512
#define NOUT  128
#define SLOPE 0.2f

// ---------------- device scratch ----------------
__device__ float  g_f1[NROWS];
__device__ float  g_f2[NROWS];
__device__ float  g_A[NROWS];
__device__ float  g_C[NROWS];
__device__ unsigned int g_bits[NROWS * 256];    // 8 MB bitpacked adj
__device__ uint4  g_UVT2[2 * 128 * 1024];       // 4 MB: {U,V} fp16 pre-swizzled B^T tiles
__device__ uint4  g_ZT[128 * 64];               // per chunk: 8 rows x 64 j fp16 (u, v, zero...)
__device__ float  g_pp[2 * NROWS * NOUT];
__device__ float  g_pn[2 * NROWS * NOUT];
__device__ float  g_zu[2 * NROWS];
__device__ float  g_zv[2 * NROWS];
__device__ unsigned int g_cnt;

// ---------------- helpers ----------------
__device__ __forceinline__ uint32_t smem_u32(const void* p) {
    uint32_t r;
    asm("{ .reg .u64 t; cvta.to.shared.u64 t, %1; cvt.u32.u64 %0, t; }" : "=r"(r) : "l"(p));
    return r;
}
#define SW128(x) ((x) ^ (((x) >> 3) & 0x70))

#define LDSM_X4(r0, r1, r2, r3, addr) \
    asm volatile("ldmatrix.sync.aligned.m8n8.x4.shared.b16 {%0,%1,%2,%3}, [%4];" \
        : "=r"(r0), "=r"(r1), "=r"(r2), "=r"(r3) : "r"(addr))

#define MMA16816(d, a0, a1, a2, a3, b0, b1) \
    asm volatile("mma.sync.aligned.m16n8k16.row.col.f32.f16.f16.f32 " \
        "{%0,%1,%2,%3},{%4,%5,%6,%7},{%8,%9},{%0,%1,%2,%3};" \
        : "+f"((d)[0]), "+f"((d)[1]), "+f"((d)[2]), "+f"((d)[3]) \
        : "r"(a0), "r"(a1), "r"(a2), "r"(a3), "r"(b0), "r"(b1))

__device__ __forceinline__ void cp_async16(uint32_t dst, const void* src) {
    asm volatile("cp.async.cg.shared.global [%0], [%1], 16;" :: "r"(dst), "l"(src) : "memory");
}
__device__ __forceinline__ void cp_async8(uint32_t dst, const void* src) {
    asm volatile("cp.async.ca.shared.global [%0], [%1], 8;" :: "r"(dst), "l"(src) : "memory");
}
#define CP_COMMIT() asm volatile("cp.async.commit_group;" ::: "memory")
#define CP_WAIT1()  asm volatile("cp.async.wait_group 1;" ::: "memory")

__device__ __forceinline__ unsigned pack_f16x2(float lo, float hi) {
    unsigned r;
    asm("cvt.rn.f16x2.f32 %0, %1, %2;" : "=r"(r) : "f"(hi), "f"(lo));
    return r;
}
__device__ __forceinline__ unsigned dup_f16(float f) {
    unsigned r;
    asm("{ .reg .f16 h; cvt.rn.f16.f32 h, %1; mov.b32 %0, {h, h}; }" : "=r"(r) : "f"(f));
    return r;
}
// pos/neg fp16x2 A-fragment pair from 2 adjacency bits + sign predicate
__device__ __forceinline__ void mkfrag(unsigned long long w, int j0, unsigned f2h, unsigned thr2,
                                       unsigned &pos, unsigned &neg) {
    unsigned x = (unsigned)(w >> j0) & 3u;
    unsigned b2 = (x & 1u) * 0x3C00u + (x >> 1) * 0x3C000000u;
    unsigned s2;
    asm("set.ge.f16x2.f16x2 %0, %1, %2;" : "=r"(s2) : "r"(f2h), "r"(thr2));
    asm("mul.rn.f16x2 %0, %1, %2;" : "=r"(pos) : "r"(b2), "r"(s2));
    asm("sub.rn.f16x2 %0, %1, %2;" : "=r"(neg) : "r"(b2), "r"(pos));
}

// ============ kA: [Wh GEMM + features + UVT/ZT] blocks + separate adj bitpack blocks ============
__global__ __launch_bounds__(256) void kA(const float* __restrict__ h, const float* __restrict__ W,
                                          const float* __restrict__ a, const int* __restrict__ adj) {
    if (blockIdx.x >= 128) {
        const int i = blockIdx.x - 128;
        const int t = threadIdx.x;
        const int l = t & 31;
        const int4* row = (const int4*)(adj + (size_t)i * NROWS);
        int4 v[8];
#pragma unroll
        for (int k = 0; k < 8; k++) v[k] = row[k * 256 + t];   // MLP 8
#pragma unroll
        for (int k = 0; k < 8; k++) {
            unsigned nib = (v[k].x != 0 ? 1u : 0u) | (v[k].y != 0 ? 2u : 0u)
                         | (v[k].z != 0 ? 4u : 0u) | (v[k].w != 0 ? 8u : 0u);
            unsigned m = nib << ((t & 7) * 4);
            m |= __shfl_xor_sync(0xffffffffu, m, 1);
            m |= __shfl_xor_sync(0xffffffffu, m, 2);
            m |= __shfl_xor_sync(0xffffffffu, m, 4);
            if ((l & 7) == 0) g_bits[(size_t)i * 256 + k * 32 + (t >> 3)] = m;
        }
        return;
    }

    __shared__ float hs[64][33];
    __shared__ float Ws[32][128];
    const int t  = threadIdx.x;
    const int i0 = blockIdx.x * 64;
    const int tx = t & 31;
    const int ty = t >> 5;

    float acc[8][4];
#pragma unroll
    for (int r = 0; r < 8; r++)
#pragma unroll
        for (int c = 0; c < 4; c++) acc[r][c] = 0.f;

    for (int k0 = 0; k0 < INP; k0 += 32) {
#pragma unroll
        for (int p = 0; p < 2; p++) {
            int u = t + p * 256;
            int r = u >> 3, kc = (u & 7) * 4;
            float4 hv = *(const float4*)(h + (size_t)(i0 + r) * INP + k0 + kc);
            hs[r][kc] = hv.x; hs[r][kc + 1] = hv.y; hs[r][kc + 2] = hv.z; hs[r][kc + 3] = hv.w;
        }
#pragma unroll
        for (int p = 0; p < 4; p++) {
            int u = t + p * 256;
            int kr = u >> 5, cc = (u & 31) * 4;
            *(float4*)&Ws[kr][cc] = *(const float4*)(W + (size_t)(k0 + kr) * NOUT + cc);
        }
        __syncthreads();
#pragma unroll
        for (int kk = 0; kk < 32; kk++) {
            float4 bv = *(float4*)&Ws[kk][tx * 4];
#pragma unroll
            for (int r = 0; r < 8; r++) {
                float av = hs[ty * 8 + r][kk];
                acc[r][0] += av * bv.x; acc[r][1] += av * bv.y;
                acc[r][2] += av * bv.z; acc[r][3] += av * bv.w;
            }
        }
        __syncthreads();
    }

    float4 a1 = __ldg((const float4*)(a + tx * 4));
    float4 a2 = __ldg((const float4*)(a + 128 + tx * 4));
    float uu[8], vv[8];
#pragma unroll
    for (int r = 0; r < 8; r++) {
        float s1 = acc[r][0] * a1.x + acc[r][1] * a1.y + acc[r][2] * a1.z + acc[r][3] * a1.w;
        float s2 = acc[r][0] * a2.x + acc[r][1] * a2.y + acc[r][2] * a2.z + acc[r][3] * a2.w;
#pragma unroll
        for (int off = 16; off > 0; off >>= 1) {
            s1 += __shfl_xor_sync(0xffffffffu, s1, off);
            s2 += __shfl_xor_sync(0xffffffffu, s2, off);
        }
        uu[r] = expf(s2);
        vv[r] = expf(SLOPE * s2);
        if (tx == r) {
            int j = i0 + ty * 8 + r;
            g_f1[j] = s1;
            g_f2[j] = s2;
            g_A[j]  = expf(s1);
            g_C[j]  = expf(SLOPE * s1);
        }
    }

    const int jbase = ty * 8;
    char* base = (char*)g_UVT2 + (size_t)blockIdx.x * 16384;
#pragma unroll
    for (int rp = 0; rp < 4; rp++) {
#pragma unroll
        for (int c = 0; c < 4; c++) {
            float U0 = uu[2 * rp] * acc[2 * rp][c],     U1 = uu[2 * rp + 1] * acc[2 * rp + 1][c];
            float V0 = vv[2 * rp] * acc[2 * rp][c],     V1 = vv[2 * rp + 1] * acc[2 * rp + 1][c];
            unsigned off = SW128((unsigned)((tx * 4 + c) * 128 + (jbase + 2 * rp) * 2));
            *(unsigned*)(base + off)            = pack_f16x2(U0, U1);
            *(unsigned*)(base + 2097152u + off) = pack_f16x2(V0, V1);
        }
    }

    {
        char* zb = (char*)g_ZT + (size_t)blockIdx.x * 1024;
        int rsel = tx & 7;
        float us = uu[0], vs = vv[0];
#pragma unroll
        for (int r = 1; r < 8; r++) if (rsel == r) { us = uu[r]; vs = vv[r]; }
        int n = tx >> 3;
        if (n < 2) {
            float val = (n == 0) ? us : vs;
            unsigned off = (unsigned)(n * 128) + (((unsigned)((jbase + rsel) * 2)) ^ ((unsigned)n << 4));
            *(__half*)(zb + off) = __float2half(val);
        }
        if (t < 192) {
            int zn = 2 + (t >> 5);
            unsigned zoff = (unsigned)(zn * 128) + ((((unsigned)(t & 31)) * 4u) ^ ((unsigned)(zn & 7) << 4));
            *(unsigned*)(zb + zoff) = 0u;
        }
    }
}

// ============ K4: register-built A-fragments, no mask SMEM ============
#define BTILE     16384
#define ZTB       1024
#define BBUF      (2 * BTILE + ZTB)              // 33792
#define DYNSMEM   (3 * BBUF)                     // 101376 (B triple-buffered)

__global__ void __launch_bounds__(512, 1) k4_hmma(float* __restrict__ out) {
    extern __shared__ __align__(16) char dyn[];
    __shared__ __align__(16) float s_f2[4096];
    __shared__ __align__(16) unsigned sbits[4 * 256];   // 4 slots x (128 rows x 2 words)

    const int tid  = threadIdx.x;
    const int wid  = tid >> 5;
    const int lane = tid & 31;
    const int rt = blockIdx.x >> 1;
    const int hh = blockIdx.x & 1;
    const int i0 = rt << 7;
    const int j0 = hh << 12;

    const uint32_t bbuf_u  = smem_u32(dyn);
    const uint32_t sbits_u = smem_u32(sbits);

    for (int q = tid; q < 4096; q += 512) s_f2[q] = g_f2[j0 + q];

    float dp[2][4][4], dn[2][4][4];
    float dzp[2][4], dzn[2][4];
#pragma unroll
    for (int mt = 0; mt < 2; mt++) {
#pragma unroll
        for (int nt = 0; nt < 4; nt++)
#pragma unroll
            for (int r = 0; r < 4; r++) { dp[mt][nt][r] = 0.f; dn[mt][nt][r] = 0.f; }
#pragma unroll
        for (int r = 0; r < 4; r++) { dzp[mt][r] = 0.f; dzn[mt][r] = 0.f; }
    }

    const int warp_m = wid >> 2;
    const int warp_n = wid & 3;
    const bool diag = (warp_m == warp_n);
    const int ib = warp_m << 5;
    const int cb = warp_n << 5;

    const int g   = lane >> 2;        // fragment group row
    const int tig = lane & 3;         // thread-in-group
    const int cr = cb + lane;
    const uint32_t brow = (uint32_t)cr * 128u, bsw = (uint32_t)(cr & 7) << 4;

    const uint32_t zn   = (uint32_t)(lane >> 2);
    const uint32_t zsw  = (zn & 7u) << 4;
    const uint32_t zrow = 2u * BTILE + zn * 128u;
    const uint32_t zkb  = ((uint32_t)tig) << 2;

    // thresholds (fp16x2, duplicated) for this lane's 4 fragment rows
    unsigned thr2_[4];
#pragma unroll
    for (int r = 0; r < 4; r++) thr2_[r] = dup_f16(-g_f1[i0 + ib + g + 8 * r]);

    auto prefetch_bits = [&](int c) {
        if (tid < 128) {
            uint32_t dst = sbits_u + (uint32_t)(c & 3) * 1024u + (uint32_t)tid * 8u;
            const unsigned* src = &g_bits[(size_t)(i0 + tid) * 256 + (unsigned)((j0 + (c << 6)) >> 5)];
            cp_async8(dst, src);
        }
    };
    auto prefetch_B = [&](int c) {
        const int nc = (hh << 6) + c;
        const uint32_t dstb = bbuf_u + (uint32_t)(c % 3) * BBUF;
        const char* srcb = (const char*)g_UVT2 + (size_t)nc * 16384;
#pragma unroll
        for (int pass = 0; pass < 4; pass++) {
            int u = tid + pass * 512;
            int m = u >> 10;
            uint32_t off = (uint32_t)(u & 1023) << 4;
            cp_async16(dstb + (uint32_t)m * BTILE + off, srcb + (size_t)m * 2097152 + off);
        }
        if (tid < 64)
            cp_async16(dstb + 2u * BTILE + (uint32_t)tid * 16u,
                       (const char*)g_ZT + (size_t)nc * 1024 + tid * 16);
    };

    // ---- prologue: group k contains B(k); bits 0..2 ride in group 0 ----
    prefetch_B(0); prefetch_bits(0); prefetch_bits(1); prefetch_bits(2);
    CP_COMMIT();                 // g0
    prefetch_B(1);
    CP_COMMIT();                 // g1

    for (int t = 0; t < 64; t++) {
        CP_WAIT1();              // groups <= t complete: B[t], bits[t+1] (bits[t] earlier)
        __syncthreads();         // cross-thread visibility of B[t] / sbits[t]

        // per-lane chunk data: adjacency words for 4 rows + fp16 f2 pairs for 8 k-pairs
        const unsigned* sb = sbits + (t & 3) * 256;
        unsigned long long w0 = *(const unsigned long long*)&sb[(ib + g) * 2];
        unsigned long long w1 = *(const unsigned long long*)&sb[(ib + g + 8) * 2];
        unsigned long long w2 = *(const unsigned long long*)&sb[(ib + g + 16) * 2];
        unsigned long long w3 = *(const unsigned long long*)&sb[(ib + g + 24) * 2];
        unsigned f2h[8];
        const int tch = t << 6;
#pragma unroll
        for (int m = 0; m < 8; m++) {
            float2 fp = *(const float2*)&s_f2[tch + (tig << 1) + (m << 3)];
            f2h[m] = pack_f16x2(fp.x, fp.y);
        }

        const uint32_t bufb = bbuf_u + (uint32_t)(t % 3) * BBUF;

#pragma unroll
        for (int ks = 0; ks < 4; ks++) {
            const int m0 = 2 * ks, m1 = 2 * ks + 1;
            const int ja = tig * 2 + 8 * m0;       // k-col base for a0/a1
            const int jb = tig * 2 + 8 * m1;       // k-col base for a2/a3
            unsigned ap0[4], an0[4], ap1[4], an1[4];
            mkfrag(w0, ja, f2h[m0], thr2_[0], ap0[0], an0[0]);
            mkfrag(w1, ja, f2h[m0], thr2_[1], ap0[1], an0[1]);
            mkfrag(w0, jb, f2h[m1], thr2_[0], ap0[2], an0[2]);
            mkfrag(w1, jb, f2h[m1], thr2_[1], ap0[3], an0[3]);
            mkfrag(w2, ja, f2h[m0], thr2_[2], ap1[0], an1[0]);
            mkfrag(w3, ja, f2h[m0], thr2_[3], ap1[1], an1[1]);
            mkfrag(w2, jb, f2h[m1], thr2_[2], ap1[2], an1[2]);
            mkfrag(w3, jb, f2h[m1], thr2_[3], ap1[3], an1[3]);

            // U part -> dp
            {
                uint32_t b0[4], b1[4];
                const uint32_t pb = bufb + brow;
                LDSM_X4(b0[0], b0[1], b0[2], b0[3], pb + ((((uint32_t)ks << 5) | 0u)  ^ bsw));
                LDSM_X4(b1[0], b1[1], b1[2], b1[3], pb + ((((uint32_t)ks << 5) | 16u) ^ bsw));
#pragma unroll
                for (int nt = 0; nt < 4; nt++) {
                    MMA16816(dp[0][nt], ap0[0], ap0[1], ap0[2], ap0[3], b0[nt], b1[nt]);
                    MMA16816(dp[1][nt], ap1[0], ap1[1], ap1[2], ap1[3], b0[nt], b1[nt]);
                }
            }
            // V part -> dn
            {
                uint32_t b0[4], b1[4];
                const uint32_t pb = bufb + BTILE + brow;
                LDSM_X4(b0[0], b0[1], b0[2], b0[3], pb + ((((uint32_t)ks << 5) | 0u)  ^ bsw));
                LDSM_X4(b1[0], b1[1], b1[2], b1[3], pb + ((((uint32_t)ks << 5) | 16u) ^ bsw));
#pragma unroll
                for (int nt = 0; nt < 4; nt++) {
                    MMA16816(dn[0][nt], an0[0], an0[1], an0[2], an0[3], b0[nt], b1[nt]);
                    MMA16816(dn[1][nt], an1[0], an1[1], an1[2], an1[3], b0[nt], b1[nt]);
                }
            }
            // Z streams (diag warps)
            if (diag) {
                const uint32_t zk = ((uint32_t)ks << 5) + zkb;
                const uint32_t a0 = bufb + zrow + (zk ^ zsw);
                const uint32_t a1 = bufb + zrow + ((zk + 16u) ^ zsw);
                uint32_t bz0, bz1;
                asm volatile("ld.shared.b32 %0, [%1];" : "=r"(bz0) : "r"(a0));
                asm volatile("ld.shared.b32 %0, [%1];" : "=r"(bz1) : "r"(a1));
                MMA16816(dzp[0], ap0[0], ap0[1], ap0[2], ap0[3], bz0, bz1);
                MMA16816(dzp[1], ap1[0], ap1[1], ap1[2], ap1[3], bz0, bz1);
                MMA16816(dzn[0], an0[0], an0[1], an0[2], an0[3], bz0, bz1);
                MMA16816(dzn[1], an1[0], an1[1], an1[2], an1[3], bz0, bz1);
            }
        }

        if (t + 2 < 64) prefetch_B(t + 2);          // buffer (t+2)%3: readers of it finished pre-barrier
        if (t + 3 < 64) prefetch_bits(t + 3);       // slot (t+3)&3 != t&3: no reader conflict
        CP_COMMIT();
    }

    // ---- write raw partials ----
    float* pdst = g_pp + (size_t)hh * (NROWS * NOUT);
    float* ndst = g_pn + (size_t)hh * (NROWS * NOUT);
#pragma unroll
    for (int mt = 0; mt < 2; mt++) {
        const int r0 = i0 + ib + mt * 16 + g;
        const int r1 = r0 + 8;
#pragma unroll
        for (int nt = 0; nt < 4; nt++) {
            const int c = cb + nt * 8 + (tig << 1);
            *(float2*)&pdst[(size_t)r0 * NOUT + c] = make_float2(dp[mt][nt][0], dp[mt][nt][1]);
            *(float2*)&pdst[(size_t)r1 * NOUT + c] = make_float2(dp[mt][nt][2], dp[mt][nt][3]);
            *(float2*)&ndst[(size_t)r0 * NOUT + c] = make_float2(dn[mt][nt][0], dn[mt][nt][1]);
            *(float2*)&ndst[(size_t)r1 * NOUT + c] = make_float2(dn[mt][nt][2], dn[mt][nt][3]);
        }
    }
    if (diag) {
#pragma unroll
        for (int mt = 0; mt < 2; mt++) {
            const int r0 = i0 + ib + mt * 16 + g;
            if (tig == 0) {
                g_zu[hh * NROWS + r0]     = dzp[mt][0];
                g_zu[hh * NROWS + r0 + 8] = dzp[mt][2];
                g_zv[hh * NROWS + r0]     = dzn[mt][1];
                g_zv[hh * NROWS + r0 + 8] = dzn[mt][3];
            }
        }
    }

    // ---- device-wide barrier (grid=128, 1 CTA/SM: all resident) ----
    __threadfence();
    __syncthreads();
    if (tid == 0) {
        unsigned t0 = atomicAdd(&g_cnt, 1u);
        unsigned target = ((t0 >> 7) + 1u) << 7;
        unsigned cur;
        do {
            asm volatile("ld.acquire.gpu.u32 %0, [%1];" : "=r"(cur) : "l"(&g_cnt));
            if (cur < target) __nanosleep(128);
        } while (cur < target);
    }
    __syncthreads();

    // ---- combine ----
    {
        const int rbase = blockIdx.x * 64;
#pragma unroll
        for (int it = 0; it < 4; it++) {
            int u = tid + it * 512;
            int r = rbase + (u >> 5);
            int c = (u & 31) * 4;
            float A = g_A[r], Cc = g_C[r];
            float z = A * (g_zu[r] + g_zu[NROWS + r]) + Cc * (g_zv[r] + g_zv[NROWS + r]);
            float zi = 1.f / z;
            const float4 p0 = *(const float4*)&g_pp[(size_t)r * NOUT + c];
            const float4 p1 = *(const float4*)&g_pp[(size_t)(NROWS + r) * NOUT + c];
            const float4 n0 = *(const float4*)&g_pn[(size_t)r * NOUT + c];
            const float4 n1 = *(const float4*)&g_pn[(size_t)(NROWS + r) * NOUT + c];
            float4 o;
            o.x = (A * (p0.x + p1.x) + Cc * (n0.x + n1.x)) * zi;
            o.y = (A * (p0.y + p1.y) + Cc * (n0.y + n1.y)) * zi;
            o.z = (A * (p0.z + p1.z) + Cc * (n0.z + n1.z)) * zi;
            o.w = (A * (p0.w + p1.w) + Cc * (n0.w + n1.w)) * zi;
            *(float4*)&out[(size_t)r * NOUT + c] = o;
        }
    }
}

// ---------------- launcher ----------------
extern "C" void kernel_launch(void* const* d_in, const int* in_sizes, int n_in,
                              void* d_out, int out_size) {
    const float* h = nullptr; const int* adj = nullptr; const float* W = nullptr; const float* a = nullptr;
    for (int k = 0; k < n_in; k++) {
        switch (in_sizes[k]) {
            case NROWS * INP:   h   = (const float*)d_in[k]; break;
            case NROWS * NROWS: adj = (const int*)d_in[k];   break;
            case INP * NOUT:    W   = (const float*)d_in[k]; break;
            case 2 * NOUT:      a   = (const float*)d_in[k]; break;
            default: break;
        }
    }
    float* out = (float*)d_out;

    cudaFuncSetAttribute(k4_hmma, cudaFuncAttributeMaxDynamicSharedMemorySize, DYNSMEM);

    kA     <<<128 + NROWS, 256>>>(h, W, a, adj);
    k4_hmma<<<128, 512, DYNSMEM>>>(out);
}

// round 12
// speedup vs baseline: 1.1637x; 1.0690x over previous
#include <cuda_runtime.h>
#include <cuda_fp16.h>
#include <stdint.h>

#define NROWS 8192
#define INP   512
#define NOUT  128
#define SLOPE 0.2f

// ---------------- device scratch ----------------
__device__ float  g_f1[NROWS];
__device__ float  g_f2[NROWS];
__device__ float  g_A[NROWS];
__device__ float  g_C[NROWS];
__device__ unsigned int g_bits[NROWS * 256];    // 8 MB bitpacked adj
__device__ uint4  g_UVT2[2 * 128 * 1024];       // 4 MB: {U,V} fp16 pre-swizzled B^T tiles
__device__ uint4  g_ZT[128 * 64];               // per chunk: 8 rows x 64 j fp16 (u, v, zero...)
__device__ float  g_pp[2 * NROWS * NOUT];
__device__ float  g_pn[2 * NROWS * NOUT];
__device__ float  g_zu[2 * NROWS];
__device__ float  g_zv[2 * NROWS];
__device__ unsigned int g_cnt;

// ---------------- helpers ----------------
__device__ __forceinline__ uint32_t smem_u32(const void* p) {
    uint32_t r;
    asm("{ .reg .u64 t; cvta.to.shared.u64 t, %1; cvt.u32.u64 %0, t; }" : "=r"(r) : "l"(p));
    return r;
}
#define SW128(x) ((x) ^ (((x) >> 3) & 0x70))

#define LDSM_X4(r0, r1, r2, r3, addr) \
    asm volatile("ldmatrix.sync.aligned.m8n8.x4.shared.b16 {%0,%1,%2,%3}, [%4];" \
        : "=r"(r0), "=r"(r1), "=r"(r2), "=r"(r3) : "r"(addr))

#define MMA16816(d, a0, a1, a2, a3, b0, b1) \
    asm volatile("mma.sync.aligned.m16n8k16.row.col.f32.f16.f16.f32 " \
        "{%0,%1,%2,%3},{%4,%5,%6,%7},{%8,%9},{%0,%1,%2,%3};" \
        : "+f"((d)[0]), "+f"((d)[1]), "+f"((d)[2]), "+f"((d)[3]) \
        : "r"(a0), "r"(a1), "r"(a2), "r"(a3), "r"(b0), "r"(b1))

__device__ __forceinline__ void cp_async16(uint32_t dst, const void* src) {
    asm volatile("cp.async.cg.shared.global [%0], [%1], 16;" :: "r"(dst), "l"(src) : "memory");
}
__device__ __forceinline__ void cp_async8(uint32_t dst, const void* src) {
    asm volatile("cp.async.ca.shared.global [%0], [%1], 8;" :: "r"(dst), "l"(src) : "memory");
}
#define CP_COMMIT() asm volatile("cp.async.commit_group;" ::: "memory")
#define CP_WAIT1()  asm volatile("cp.async.wait_group 1;" ::: "memory")

__device__ __forceinline__ unsigned pack_f16x2(float lo, float hi) {
    unsigned r;
    asm("cvt.rn.f16x2.f32 %0, %1, %2;" : "=r"(r) : "f"(hi), "f"(lo));
    return r;
}
__device__ __forceinline__ unsigned prmt(unsigned a, unsigned b, unsigned s) {
    unsigned r;
    asm("prmt.b32 %0, %1, %2, %3;" : "=r"(r) : "r"(a), "r"(b), "r"(s));
    return r;
}

// ============ kA: [Wh GEMM + features + UVT/ZT] blocks + fat adj bitpack blocks ============
// blocks [0,128): GEMM, 64 rows each. blocks [128, 128+1024): pack 8 adj rows each.
__global__ __launch_bounds__(256) void kA(const float* __restrict__ h, const float* __restrict__ W,
                                          const float* __restrict__ a, const int* __restrict__ adj) {
    if (blockIdx.x >= 128) {
        // thread t packs 32 contiguous ints of each of 8 rows: no cross-lane ops,
        // 8x LDG.128 per row (MLP 8, x2 with unroll), coalesced 1KB word stores.
        const int rb = (blockIdx.x - 128) * 8;
        const int t  = threadIdx.x;
#pragma unroll 2
        for (int r = 0; r < 8; r++) {
            const int4* src = (const int4*)(adj + (size_t)(rb + r) * NROWS) + t * 8;
            int4 v[8];
#pragma unroll
            for (int k = 0; k < 8; k++) v[k] = __ldg(&src[k]);
            unsigned w = 0;
#pragma unroll
            for (int k = 0; k < 8; k++) {
                w += (unsigned)v[k].x << (k * 4 + 0);
                w += (unsigned)v[k].y << (k * 4 + 1);
                w += (unsigned)v[k].z << (k * 4 + 2);
                w += (unsigned)v[k].w << (k * 4 + 3);
            }
            g_bits[(size_t)(rb + r) * 256 + t] = w;
        }
        return;
    }

    __shared__ float hs[64][33];
    __shared__ float Ws[32][128];
    const int t  = threadIdx.x;
    const int i0 = blockIdx.x * 64;
    const int tx = t & 31;
    const int ty = t >> 5;

    float acc[8][4];
#pragma unroll
    for (int r = 0; r < 8; r++)
#pragma unroll
        for (int c = 0; c < 4; c++) acc[r][c] = 0.f;

    for (int k0 = 0; k0 < INP; k0 += 32) {
#pragma unroll
        for (int p = 0; p < 2; p++) {
            int u = t + p * 256;
            int r = u >> 3, kc = (u & 7) * 4;
            float4 hv = *(const float4*)(h + (size_t)(i0 + r) * INP + k0 + kc);
            hs[r][kc] = hv.x; hs[r][kc + 1] = hv.y; hs[r][kc + 2] = hv.z; hs[r][kc + 3] = hv.w;
        }
#pragma unroll
        for (int p = 0; p < 4; p++) {
            int u = t + p * 256;
            int kr = u >> 5, cc = (u & 31) * 4;
            *(float4*)&Ws[kr][cc] = *(const float4*)(W + (size_t)(k0 + kr) * NOUT + cc);
        }
        __syncthreads();
#pragma unroll
        for (int kk = 0; kk < 32; kk++) {
            float4 bv = *(float4*)&Ws[kk][tx * 4];
#pragma unroll
            for (int r = 0; r < 8; r++) {
                float av = hs[ty * 8 + r][kk];
                acc[r][0] += av * bv.x; acc[r][1] += av * bv.y;
                acc[r][2] += av * bv.z; acc[r][3] += av * bv.w;
            }
        }
        __syncthreads();
    }

    float4 a1 = __ldg((const float4*)(a + tx * 4));
    float4 a2 = __ldg((const float4*)(a + 128 + tx * 4));
    float uu[8], vv[8];
#pragma unroll
    for (int r = 0; r < 8; r++) {
        float s1 = acc[r][0] * a1.x + acc[r][1] * a1.y + acc[r][2] * a1.z + acc[r][3] * a1.w;
        float s2 = acc[r][0] * a2.x + acc[r][1] * a2.y + acc[r][2] * a2.z + acc[r][3] * a2.w;
#pragma unroll
        for (int off = 16; off > 0; off >>= 1) {
            s1 += __shfl_xor_sync(0xffffffffu, s1, off);
            s2 += __shfl_xor_sync(0xffffffffu, s2, off);
        }
        uu[r] = expf(s2);
        vv[r] = expf(SLOPE * s2);
        if (tx == r) {
            int j = i0 + ty * 8 + r;
            g_f1[j] = s1;
            g_f2[j] = s2;
            g_A[j]  = expf(s1);
            g_C[j]  = expf(SLOPE * s1);
        }
    }

    const int jbase = ty * 8;
    char* base = (char*)g_UVT2 + (size_t)blockIdx.x * 16384;
#pragma unroll
    for (int rp = 0; rp < 4; rp++) {
#pragma unroll
        for (int c = 0; c < 4; c++) {
            float U0 = uu[2 * rp] * acc[2 * rp][c],     U1 = uu[2 * rp + 1] * acc[2 * rp + 1][c];
            float V0 = vv[2 * rp] * acc[2 * rp][c],     V1 = vv[2 * rp + 1] * acc[2 * rp + 1][c];
            unsigned off = SW128((unsigned)((tx * 4 + c) * 128 + (jbase + 2 * rp) * 2));
            *(unsigned*)(base + off)            = pack_f16x2(U0, U1);
            *(unsigned*)(base + 2097152u + off) = pack_f16x2(V0, V1);
        }
    }

    {
        char* zb = (char*)g_ZT + (size_t)blockIdx.x * 1024;
        int rsel = tx & 7;
        float us = uu[0], vs = vv[0];
#pragma unroll
        for (int r = 1; r < 8; r++) if (rsel == r) { us = uu[r]; vs = vv[r]; }
        int n = tx >> 3;
        if (n < 2) {
            float val = (n == 0) ? us : vs;
            unsigned off = (unsigned)(n * 128) + (((unsigned)((jbase + rsel) * 2)) ^ ((unsigned)n << 4));
            *(__half*)(zb + off) = __float2half(val);
        }
        if (t < 192) {
            int zn = 2 + (t >> 5);
            unsigned zoff = (unsigned)(zn * 128) + ((((unsigned)(t & 31)) * 4u) ^ ((unsigned)(zn & 7) << 4));
            *(unsigned*)(zb + zoff) = 0u;
        }
    }
}

// ============ K4: fp16 HMMA masked GEMMs (SMEM masks, triple-buffered B) ============
#define MASKBUF   32768
#define BTILE     16384
#define ZTB       1024
#define BBUF      (2 * BTILE + ZTB)              // 33792
#define DYNSMEM   (2 * MASKBUF + 3 * BBUF)       // 166912

__global__ void __launch_bounds__(512, 1) k4_hmma(float* __restrict__ out) {
    extern __shared__ __align__(16) char dyn[];
    __shared__ float s_f1[128];
    __shared__ __align__(16) float s_f2[4096];
    __shared__ __align__(16) unsigned sbits[3 * 256];

    const int tid  = threadIdx.x;
    const int wid  = tid >> 5;
    const int lane = tid & 31;
    const int rt = blockIdx.x >> 1;
    const int hh = blockIdx.x & 1;
    const int i0 = rt << 7;
    const int j0 = hh << 12;

    const uint32_t dbase  = smem_u32(dyn);
    const uint32_t bbuf_u = dbase + 2u * MASKBUF;
    const uint32_t sbits_u = smem_u32(sbits);

    if (tid < 128) s_f1[tid] = g_f1[i0 + tid];
    for (int q = tid; q < 4096; q += 512) s_f2[q] = g_f2[j0 + q];
    __syncthreads();

    float dp[2][4][4], dn[2][4][4];
    float dzp[2][4], dzn[2][4];
#pragma unroll
    for (int mt = 0; mt < 2; mt++) {
#pragma unroll
        for (int nt = 0; nt < 4; nt++)
#pragma unroll
            for (int r = 0; r < 4; r++) { dp[mt][nt][r] = 0.f; dn[mt][nt][r] = 0.f; }
#pragma unroll
        for (int r = 0; r < 4; r++) { dzp[mt][r] = 0.f; dzn[mt][r] = 0.f; }
    }

    const int warp_m = wid >> 2;
    const int warp_n = wid & 3;
    const bool diag = (warp_m == warp_n);
    const int ib = warp_m << 5;
    const int cb = warp_n << 5;

    const int ri0 = ib + (lane & 15);
    const int ri1 = ri0 + 16;
    const uint32_t arow0 = (uint32_t)ri0 * 128u, asw0 = (uint32_t)(ri0 & 7) << 4;
    const uint32_t arow1 = (uint32_t)ri1 * 128u, asw1 = (uint32_t)(ri1 & 7) << 4;
    const uint32_t akh   = (uint32_t)(lane >> 4) << 4;
    const int cr = cb + lane;
    const uint32_t brow = (uint32_t)cr * 128u, bsw = (uint32_t)(cr & 7) << 4;

    const uint32_t zn   = (uint32_t)(lane >> 2);
    const uint32_t zsw  = (zn & 7u) << 4;
    const uint32_t zrow = 2u * BTILE + zn * 128u;
    const uint32_t zkb  = ((uint32_t)(lane & 3)) << 2;

    auto prefetch_bits = [&](int c) {
        if (tid < 128) {
            uint32_t dst = sbits_u + (uint32_t)(c % 3) * 1024u + (uint32_t)tid * 8u;
            const unsigned* src = &g_bits[(size_t)(i0 + tid) * 256 + (unsigned)((j0 + (c << 6)) >> 5)];
            cp_async8(dst, src);
        }
    };

    auto build_masks = [&](int c, int mb) {
        char* mdst = dyn + mb * MASKBUF;
        const int tch = c << 6;
        const unsigned* sb = sbits + (c % 3) * 256;
#pragma unroll
        for (int un = 0; un < 2; un++) {
            const int unit = (tid << 1) | un;
            const int i  = unit >> 3;
            const int jl = (unit & 7) << 3;
            const unsigned word = sb[i * 2 + (jl >> 5)];
            const unsigned bits8 = (word >> (jl & 31)) & 0xFFu;
            const float thr = -s_f1[i];
            const float4 fA = *(const float4*)&s_f2[tch + jl];
            const float4 fB = *(const float4*)&s_f2[tch + jl + 4];
            const float fs[8] = {fA.x, fA.y, fA.z, fA.w, fB.x, fB.y, fB.z, fB.w};
            unsigned pn[8];
#pragma unroll
            for (int e = 0; e < 8; e++) {
                unsigned sel = (fs[e] >= thr) ? 0x00003C00u : 0x3C000000u;
                pn[e] = ((bits8 >> e) & 1u) * sel;
            }
            uint4 wp4, wn4;
            wp4.x = prmt(pn[0], pn[1], 0x5410u); wn4.x = prmt(pn[0], pn[1], 0x7632u);
            wp4.y = prmt(pn[2], pn[3], 0x5410u); wn4.y = prmt(pn[2], pn[3], 0x7632u);
            wp4.z = prmt(pn[4], pn[5], 0x5410u); wn4.z = prmt(pn[4], pn[5], 0x7632u);
            wp4.w = prmt(pn[6], pn[7], 0x5410u); wn4.w = prmt(pn[6], pn[7], 0x7632u);
            const uint32_t off = (uint32_t)i * 128u + (((uint32_t)(jl << 1)) ^ ((uint32_t)(i & 7) << 4));
            *(uint4*)(mdst + off)          = wp4;
            *(uint4*)(mdst + 16384 + off)  = wn4;
        }
    };

    auto prefetch_B = [&](int c) {
        const int nc = (hh << 6) + c;
        const uint32_t dstb = bbuf_u + (uint32_t)(c % 3) * BBUF;
        const char* srcb = (const char*)g_UVT2 + (size_t)nc * 16384;
#pragma unroll
        for (int pass = 0; pass < 4; pass++) {
            int u = tid + pass * 512;
            int m = u >> 10;
            uint32_t off = (uint32_t)(u & 1023) << 4;
            cp_async16(dstb + (uint32_t)m * BTILE + off, srcb + (size_t)m * 2097152 + off);
        }
        if (tid < 64)
            cp_async16(dstb + 2u * BTILE + (uint32_t)tid * 16u,
                       (const char*)g_ZT + (size_t)nc * 1024 + tid * 16);
    };

    // ---- prologue ----
    prefetch_bits(0);
    prefetch_bits(1);
    prefetch_B(0);
    CP_COMMIT();                 // g1: B0, z0, bits0, bits1
    prefetch_bits(2);
    prefetch_B(1);
    CP_COMMIT();                 // g2: B1, z1, bits2
    CP_WAIT1();                  // g1 complete
    __syncthreads();
    build_masks(0, 0);

    for (int t = 0; t < 64; t++) {
        CP_WAIT1();              // B[t], bits[t+2] complete
        __syncthreads();         // masks[t] visible

        const uint32_t mpos = dbase + (uint32_t)(t & 1) * MASKBUF;
        const uint32_t mneg = mpos + 16384u;
        const uint32_t bufb = bbuf_u + (uint32_t)(t % 3) * BBUF;

#pragma unroll
        for (int ks = 0; ks < 4; ks++) {
            const uint32_t joff = ((uint32_t)ks << 5) | akh;
            uint32_t ap0[4], ap1[4], an0[4], an1[4];
            LDSM_X4(ap0[0], ap0[1], ap0[2], ap0[3], mpos + arow0 + (joff ^ asw0));
            LDSM_X4(ap1[0], ap1[1], ap1[2], ap1[3], mpos + arow1 + (joff ^ asw1));
            LDSM_X4(an0[0], an0[1], an0[2], an0[3], mneg + arow0 + (joff ^ asw0));
            LDSM_X4(an1[0], an1[1], an1[2], an1[3], mneg + arow1 + (joff ^ asw1));

            {
                uint32_t b0[4], b1[4];
                const uint32_t pb = bufb + brow;
                LDSM_X4(b0[0], b0[1], b0[2], b0[3], pb + ((((uint32_t)ks << 5) | 0u)  ^ bsw));
                LDSM_X4(b1[0], b1[1], b1[2], b1[3], pb + ((((uint32_t)ks << 5) | 16u) ^ bsw));
#pragma unroll
                for (int nt = 0; nt < 4; nt++) {
                    MMA16816(dp[0][nt], ap0[0], ap0[1], ap0[2], ap0[3], b0[nt], b1[nt]);
                    MMA16816(dp[1][nt], ap1[0], ap1[1], ap1[2], ap1[3], b0[nt], b1[nt]);
                }
            }
            {
                uint32_t b0[4], b1[4];
                const uint32_t pb = bufb + BTILE + brow;
                LDSM_X4(b0[0], b0[1], b0[2], b0[3], pb + ((((uint32_t)ks << 5) | 0u)  ^ bsw));
                LDSM_X4(b1[0], b1[1], b1[2], b1[3], pb + ((((uint32_t)ks << 5) | 16u) ^ bsw));
#pragma unroll
                for (int nt = 0; nt < 4; nt++) {
                    MMA16816(dn[0][nt], an0[0], an0[1], an0[2], an0[3], b0[nt], b1[nt]);
                    MMA16816(dn[1][nt], an1[0], an1[1], an1[2], an1[3], b0[nt], b1[nt]);
                }
            }
            if (diag) {
                const uint32_t zk = ((uint32_t)ks << 5) + zkb;
                const uint32_t a0 = bufb + zrow + (zk ^ zsw);
                const uint32_t a1 = bufb + zrow + ((zk + 16u) ^ zsw);
                uint32_t bz0, bz1;
                asm volatile("ld.shared.b32 %0, [%1];" : "=r"(bz0) : "r"(a0));
                asm volatile("ld.shared.b32 %0, [%1];" : "=r"(bz1) : "r"(a1));
                MMA16816(dzp[0], ap0[0], ap0[1], ap0[2], ap0[3], bz0, bz1);
                MMA16816(dzp[1], ap1[0], ap1[1], ap1[2], ap1[3], bz0, bz1);
                MMA16816(dzn[0], an0[0], an0[1], an0[2], an0[3], bz0, bz1);
                MMA16816(dzn[1], an1[0], an1[1], an1[2], an1[3], bz0, bz1);
            }
        }

        if (t < 63) build_masks(t + 1, (t + 1) & 1);
        if (t + 2 < 64) {
            prefetch_B(t + 2);           // buffer (t+2)%3: distinct from t%3, (t+1)%3 — no race
            if (t + 3 < 64) prefetch_bits(t + 3);
        }
        CP_COMMIT();
    }

    // ---- write raw partials ----
    float* pdst = g_pp + (size_t)hh * (NROWS * NOUT);
    float* ndst = g_pn + (size_t)hh * (NROWS * NOUT);
#pragma unroll
    for (int mt = 0; mt < 2; mt++) {
        const int r0 = i0 + ib + mt * 16 + (lane >> 2);
        const int r1 = r0 + 8;
#pragma unroll
        for (int nt = 0; nt < 4; nt++) {
            const int c = cb + nt * 8 + ((lane & 3) << 1);
            *(float2*)&pdst[(size_t)r0 * NOUT + c] = make_float2(dp[mt][nt][0], dp[mt][nt][1]);
            *(float2*)&pdst[(size_t)r1 * NOUT + c] = make_float2(dp[mt][nt][2], dp[mt][nt][3]);
            *(float2*)&ndst[(size_t)r0 * NOUT + c] = make_float2(dn[mt][nt][0], dn[mt][nt][1]);
            *(float2*)&ndst[(size_t)r1 * NOUT + c] = make_float2(dn[mt][nt][2], dn[mt][nt][3]);
        }
    }
    if (diag) {
#pragma unroll
        for (int mt = 0; mt < 2; mt++) {
            const int r0 = i0 + ib + mt * 16 + (lane >> 2);
            if ((lane & 3) == 0) {
                g_zu[hh * NROWS + r0]     = dzp[mt][0];
                g_zu[hh * NROWS + r0 + 8] = dzp[mt][2];
                g_zv[hh * NROWS + r0]     = dzn[mt][1];
                g_zv[hh * NROWS + r0 + 8] = dzn[mt][3];
            }
        }
    }

    // ---- device-wide barrier ----
    __threadfence();
    __syncthreads();
    if (tid == 0) {
        unsigned t0 = atomicAdd(&g_cnt, 1u);
        unsigned target = ((t0 >> 7) + 1u) << 7;
        unsigned cur;
        do {
            asm volatile("ld.acquire.gpu.u32 %0, [%1];" : "=r"(cur) : "l"(&g_cnt));
            if (cur < target) __nanosleep(128);
        } while (cur < target);
    }
    __syncthreads();

    // ---- combine ----
    {
        const int rbase = blockIdx.x * 64;
#pragma unroll
        for (int it = 0; it < 4; it++) {
            int u = tid + it * 512;
            int r = rbase + (u >> 5);
            int c = (u & 31) * 4;
            float A = g_A[r], Cc = g_C[r];
            float z = A * (g_zu[r] + g_zu[NROWS + r]) + Cc * (g_zv[r] + g_zv[NROWS + r]);
            float zi = 1.f / z;
            const float4 p0 = *(const float4*)&g_pp[(size_t)r * NOUT + c];
            const float4 p1 = *(const float4*)&g_pp[(size_t)(NROWS + r) * NOUT + c];
            const float4 n0 = *(const float4*)&g_pn[(size_t)r * NOUT + c];
            const float4 n1 = *(const float4*)&g_pn[(size_t)(NROWS + r) * NOUT + c];
            float4 o;
            o.x = (A * (p0.x + p1.x) + Cc * (n0.x + n1.x)) * zi;
            o.y = (A * (p0.y + p1.y) + Cc * (n0.y + n1.y)) * zi;
            o.z = (A * (p0.z + p1.z) + Cc * (n0.z + n1.z)) * zi;
            o.w = (A * (p0.w + p1.w) + Cc * (n0.w + n1.w)) * zi;
            *(float4*)&out[(size_t)r * NOUT + c] = o;
        }
    }
}

// ---------------- launcher ----------------
extern "C" void kernel_launch(void* const* d_in, const int* in_sizes, int n_in,
                              void* d_out, int out_size) {
    const float* h = nullptr; const int* adj = nullptr; const float* W = nullptr; const float* a = nullptr;
    for (int k = 0; k < n_in; k++) {
        switch (in_sizes[k]) {
            case NROWS * INP:   h   = (const float*)d_in[k]; break;
            case NROWS * NROWS: adj = (const int*)d_in[k];   break;
            case INP * NOUT:    W   = (const float*)d_in[k]; break;
            case 2 * NOUT:      a   = (const float*)d_in[k]; break;
            default: break;
        }
    }
    float* out = (float*)d_out;

    cudaFuncSetAttribute(k4_hmma, cudaFuncAttributeMaxDynamicSharedMemorySize, DYNSMEM);

    kA     <<<128 + 1024, 256>>>(h, W, a, adj);
    k4_hmma<<<128, 512, DYNSMEM>>>(out);
}

// round 13
// speedup vs baseline: 1.2467x; 1.0713x over previous
#include <cuda_runtime.h>
#include <cuda_fp16.h>
#include <stdint.h>

#define NROWS 8192
#define INP   512
#define NOUT  128
#define SLOPE 0.2f

// ---------------- device scratch ----------------
__device__ float  g_f1[NROWS];
__device__ float  g_f2[NROWS];
__device__ float  g_A[NROWS];
__device__ float  g_C[NROWS];
__device__ unsigned int g_bits[NROWS * 256];    // 8 MB bitpacked adj
__device__ uint4  g_UVT2[2 * 128 * 1024];       // 4 MB: {U,V} fp16 pre-swizzled B^T tiles
__device__ uint4  g_ZT[128 * 64];               // per chunk: 8 rows x 64 j fp16 (u, v, zero...)
__device__ float  g_pp[2 * NROWS * NOUT];
__device__ float  g_pn[2 * NROWS * NOUT];
__device__ float  g_zu[2 * NROWS];
__device__ float  g_zv[2 * NROWS];
__device__ unsigned int g_cnt;

// ---------------- helpers ----------------
__device__ __forceinline__ uint32_t smem_u32(const void* p) {
    uint32_t r;
    asm("{ .reg .u64 t; cvta.to.shared.u64 t, %1; cvt.u32.u64 %0, t; }" : "=r"(r) : "l"(p));
    return r;
}
#define SW128(x) ((x) ^ (((x) >> 3) & 0x70))

#define LDSM_X4(r0, r1, r2, r3, addr) \
    asm volatile("ldmatrix.sync.aligned.m8n8.x4.shared.b16 {%0,%1,%2,%3}, [%4];" \
        : "=r"(r0), "=r"(r1), "=r"(r2), "=r"(r3) : "r"(addr))

#define MMA16816(d, a0, a1, a2, a3, b0, b1) \
    asm volatile("mma.sync.aligned.m16n8k16.row.col.f32.f16.f16.f32 " \
        "{%0,%1,%2,%3},{%4,%5,%6,%7},{%8,%9},{%0,%1,%2,%3};" \
        : "+f"((d)[0]), "+f"((d)[1]), "+f"((d)[2]), "+f"((d)[3]) \
        : "r"(a0), "r"(a1), "r"(a2), "r"(a3), "r"(b0), "r"(b1))

__device__ __forceinline__ void cp_async16(uint32_t dst, const void* src) {
    asm volatile("cp.async.cg.shared.global [%0], [%1], 16;" :: "r"(dst), "l"(src) : "memory");
}
__device__ __forceinline__ void cp_async8(uint32_t dst, const void* src) {
    asm volatile("cp.async.ca.shared.global [%0], [%1], 8;" :: "r"(dst), "l"(src) : "memory");
}
#define CP_COMMIT() asm volatile("cp.async.commit_group;" ::: "memory")
#define CP_WAIT1()  asm volatile("cp.async.wait_group 1;" ::: "memory")

__device__ __forceinline__ unsigned pack_f16x2(float lo, float hi) {
    unsigned r;
    asm("cvt.rn.f16x2.f32 %0, %1, %2;" : "=r"(r) : "f"(hi), "f"(lo));
    return r;
}
__device__ __forceinline__ unsigned prmt(unsigned a, unsigned b, unsigned s) {
    unsigned r;
    asm("prmt.b32 %0, %1, %2, %3;" : "=r"(r) : "r"(a), "r"(b), "r"(s));
    return r;
}

// ============ kA: [Wh GEMM + features + UVT/ZT] blocks + adj bitpack blocks (R8 layout) ============
__global__ __launch_bounds__(256) void kA(const float* __restrict__ h, const float* __restrict__ W,
                                          const float* __restrict__ a, const int* __restrict__ adj) {
    if (blockIdx.x >= 128) {
        const int i = blockIdx.x - 128;
        const int w = threadIdx.x >> 5, lane = threadIdx.x & 31;
        const int* row = adj + (size_t)i * NROWS;
#pragma unroll
        for (int q = 0; q < 32; q++) {
            int widx = w + q * 8;
            int v = row[widx * 32 + lane];
            unsigned m = __ballot_sync(0xffffffffu, v != 0);
            if (lane == 0) g_bits[(size_t)i * 256 + widx] = m;
        }
        return;
    }

    __shared__ float hs[64][33];
    __shared__ float Ws[32][128];
    const int t  = threadIdx.x;
    const int i0 = blockIdx.x * 64;
    const int tx = t & 31;
    const int ty = t >> 5;

    float acc[8][4];
#pragma unroll
    for (int r = 0; r < 8; r++)
#pragma unroll
        for (int c = 0; c < 4; c++) acc[r][c] = 0.f;

    for (int k0 = 0; k0 < INP; k0 += 32) {
#pragma unroll
        for (int p = 0; p < 2; p++) {
            int u = t + p * 256;
            int r = u >> 3, kc = (u & 7) * 4;
            float4 hv = *(const float4*)(h + (size_t)(i0 + r) * INP + k0 + kc);
            hs[r][kc] = hv.x; hs[r][kc + 1] = hv.y; hs[r][kc + 2] = hv.z; hs[r][kc + 3] = hv.w;
        }
#pragma unroll
        for (int p = 0; p < 4; p++) {
            int u = t + p * 256;
            int kr = u >> 5, cc = (u & 31) * 4;
            *(float4*)&Ws[kr][cc] = *(const float4*)(W + (size_t)(k0 + kr) * NOUT + cc);
        }
        __syncthreads();
#pragma unroll
        for (int kk = 0; kk < 32; kk++) {
            float4 bv = *(float4*)&Ws[kk][tx * 4];
#pragma unroll
            for (int r = 0; r < 8; r++) {
                float av = hs[ty * 8 + r][kk];
                acc[r][0] += av * bv.x; acc[r][1] += av * bv.y;
                acc[r][2] += av * bv.z; acc[r][3] += av * bv.w;
            }
        }
        __syncthreads();
    }

    float4 a1 = __ldg((const float4*)(a + tx * 4));
    float4 a2 = __ldg((const float4*)(a + 128 + tx * 4));
    float uu[8], vv[8];
#pragma unroll
    for (int r = 0; r < 8; r++) {
        float s1 = acc[r][0] * a1.x + acc[r][1] * a1.y + acc[r][2] * a1.z + acc[r][3] * a1.w;
        float s2 = acc[r][0] * a2.x + acc[r][1] * a2.y + acc[r][2] * a2.z + acc[r][3] * a2.w;
#pragma unroll
        for (int off = 16; off > 0; off >>= 1) {
            s1 += __shfl_xor_sync(0xffffffffu, s1, off);
            s2 += __shfl_xor_sync(0xffffffffu, s2, off);
        }
        uu[r] = expf(s2);
        vv[r] = expf(SLOPE * s2);
        if (tx == r) {
            int j = i0 + ty * 8 + r;
            g_f1[j] = s1;
            g_f2[j] = s2;
            g_A[j]  = expf(s1);
            g_C[j]  = expf(SLOPE * s1);
        }
    }

    const int jbase = ty * 8;
    char* base = (char*)g_UVT2 + (size_t)blockIdx.x * 16384;
#pragma unroll
    for (int rp = 0; rp < 4; rp++) {
#pragma unroll
        for (int c = 0; c < 4; c++) {
            float U0 = uu[2 * rp] * acc[2 * rp][c],     U1 = uu[2 * rp + 1] * acc[2 * rp + 1][c];
            float V0 = vv[2 * rp] * acc[2 * rp][c],     V1 = vv[2 * rp + 1] * acc[2 * rp + 1][c];
            unsigned off = SW128((unsigned)((tx * 4 + c) * 128 + (jbase + 2 * rp) * 2));
            *(unsigned*)(base + off)            = pack_f16x2(U0, U1);
            *(unsigned*)(base + 2097152u + off) = pack_f16x2(V0, V1);
        }
    }

    {
        char* zb = (char*)g_ZT + (size_t)blockIdx.x * 1024;
        int rsel = tx & 7;
        float us = uu[0], vs = vv[0];
#pragma unroll
        for (int r = 1; r < 8; r++) if (rsel == r) { us = uu[r]; vs = vv[r]; }
        int n = tx >> 3;
        if (n < 2) {
            float val = (n == 0) ? us : vs;
            unsigned off = (unsigned)(n * 128) + (((unsigned)((jbase + rsel) * 2)) ^ ((unsigned)n << 4));
            *(__half*)(zb + off) = __float2half(val);
        }
        if (t < 192) {
            int zn = 2 + (t >> 5);
            unsigned zoff = (unsigned)(zn * 128) + ((((unsigned)(t & 31)) * 4u) ^ ((unsigned)(zn & 7) << 4));
            *(unsigned*)(zb + zoff) = 0u;
        }
    }
}

// ============ K4: fp16 HMMA masked GEMMs, Z distributed by warp_n==ks ============
#define MASKBUF   32768
#define BTILE     16384
#define ZTB       1024
#define BBUF      (2 * BTILE + ZTB)              // 33792
#define DYNSMEM   (2 * MASKBUF + 3 * BBUF)       // 166912

__global__ void __launch_bounds__(512, 1) k4_hmma(float* __restrict__ out) {
    extern __shared__ __align__(16) char dyn[];
    __shared__ float s_f1[128];
    __shared__ __align__(16) float s_f2[4096];
    __shared__ __align__(16) unsigned sbits[3 * 256];

    const int tid  = threadIdx.x;
    const int wid  = tid >> 5;
    const int lane = tid & 31;
    const int rt = blockIdx.x >> 1;
    const int hh = blockIdx.x & 1;
    const int i0 = rt << 7;
    const int j0 = hh << 12;

    const uint32_t dbase  = smem_u32(dyn);
    const uint32_t bbuf_u = dbase + 2u * MASKBUF;
    const uint32_t sbits_u = smem_u32(sbits);

    if (tid < 128) s_f1[tid] = g_f1[i0 + tid];
    for (int q = tid; q < 4096; q += 512) s_f2[q] = g_f2[j0 + q];
    __syncthreads();

    float dp[2][4][4], dn[2][4][4];
    float dzp[2][4], dzn[2][4];
#pragma unroll
    for (int mt = 0; mt < 2; mt++) {
#pragma unroll
        for (int nt = 0; nt < 4; nt++)
#pragma unroll
            for (int r = 0; r < 4; r++) { dp[mt][nt][r] = 0.f; dn[mt][nt][r] = 0.f; }
#pragma unroll
        for (int r = 0; r < 4; r++) { dzp[mt][r] = 0.f; dzn[mt][r] = 0.f; }
    }

    const int warp_m = wid >> 2;
    const int warp_n = wid & 3;
    const int ib = warp_m << 5;
    const int cb = warp_n << 5;

    const int ri0 = ib + (lane & 15);
    const int ri1 = ri0 + 16;
    const uint32_t arow0 = (uint32_t)ri0 * 128u, asw0 = (uint32_t)(ri0 & 7) << 4;
    const uint32_t arow1 = (uint32_t)ri1 * 128u, asw1 = (uint32_t)(ri1 & 7) << 4;
    const uint32_t akh   = (uint32_t)(lane >> 4) << 4;
    const int cr = cb + lane;
    const uint32_t brow = (uint32_t)cr * 128u, bsw = (uint32_t)(cr & 7) << 4;

    const uint32_t zn   = (uint32_t)(lane >> 2);
    const uint32_t zsw  = (zn & 7u) << 4;
    const uint32_t zrow = 2u * BTILE + zn * 128u;
    const uint32_t zkb  = ((uint32_t)(lane & 3)) << 2;

    auto prefetch_bits = [&](int c) {
        if (tid < 128) {
            uint32_t dst = sbits_u + (uint32_t)(c % 3) * 1024u + (uint32_t)tid * 8u;
            const unsigned* src = &g_bits[(size_t)(i0 + tid) * 256 + (unsigned)((j0 + (c << 6)) >> 5)];
            cp_async8(dst, src);
        }
    };

    auto build_masks = [&](int c, int mb) {
        char* mdst = dyn + mb * MASKBUF;
        const int tch = c << 6;
        const unsigned* sb = sbits + (c % 3) * 256;
#pragma unroll
        for (int un = 0; un < 2; un++) {
            const int unit = (tid << 1) | un;
            const int i  = unit >> 3;
            const int jl = (unit & 7) << 3;
            const unsigned word = sb[i * 2 + (jl >> 5)];
            const unsigned bits8 = (word >> (jl & 31)) & 0xFFu;
            const float thr = -s_f1[i];
            const float4 fA = *(const float4*)&s_f2[tch + jl];
            const float4 fB = *(const float4*)&s_f2[tch + jl + 4];
            const float fs[8] = {fA.x, fA.y, fA.z, fA.w, fB.x, fB.y, fB.z, fB.w};
            unsigned pn[8];
#pragma unroll
            for (int e = 0; e < 8; e++) {
                unsigned sel = (fs[e] >= thr) ? 0x00003C00u : 0x3C000000u;
                pn[e] = ((bits8 >> e) & 1u) * sel;
            }
            uint4 wp4, wn4;
            wp4.x = prmt(pn[0], pn[1], 0x5410u); wn4.x = prmt(pn[0], pn[1], 0x7632u);
            wp4.y = prmt(pn[2], pn[3], 0x5410u); wn4.y = prmt(pn[2], pn[3], 0x7632u);
            wp4.z = prmt(pn[4], pn[5], 0x5410u); wn4.z = prmt(pn[4], pn[5], 0x7632u);
            wp4.w = prmt(pn[6], pn[7], 0x5410u); wn4.w = prmt(pn[6], pn[7], 0x7632u);
            const uint32_t off = (uint32_t)i * 128u + (((uint32_t)(jl << 1)) ^ ((uint32_t)(i & 7) << 4));
            *(uint4*)(mdst + off)          = wp4;
            *(uint4*)(mdst + 16384 + off)  = wn4;
        }
    };

    auto prefetch_B = [&](int c) {
        const int nc = (hh << 6) + c;
        const uint32_t dstb = bbuf_u + (uint32_t)(c % 3) * BBUF;
        const char* srcb = (const char*)g_UVT2 + (size_t)nc * 16384;
#pragma unroll
        for (int pass = 0; pass < 4; pass++) {
            int u = tid + pass * 512;
            int m = u >> 10;
            uint32_t off = (uint32_t)(u & 1023) << 4;
            cp_async16(dstb + (uint32_t)m * BTILE + off, srcb + (size_t)m * 2097152 + off);
        }
        if (tid < 64)
            cp_async16(dstb + 2u * BTILE + (uint32_t)tid * 16u,
                       (const char*)g_ZT + (size_t)nc * 1024 + tid * 16);
    };

    // ---- prologue ----
    prefetch_bits(0);
    prefetch_bits(1);
    prefetch_B(0);
    CP_COMMIT();
    prefetch_bits(2);
    prefetch_B(1);
    CP_COMMIT();
    CP_WAIT1();
    __syncthreads();
    build_masks(0, 0);

    for (int t = 0; t < 64; t++) {
        CP_WAIT1();
        __syncthreads();

        const uint32_t mpos = dbase + (uint32_t)(t & 1) * MASKBUF;
        const uint32_t mneg = mpos + 16384u;
        const uint32_t bufb = bbuf_u + (uint32_t)(t % 3) * BBUF;

#pragma unroll
        for (int ks = 0; ks < 4; ks++) {
            const uint32_t joff = ((uint32_t)ks << 5) | akh;
            uint32_t ap0[4], ap1[4], an0[4], an1[4];
            LDSM_X4(ap0[0], ap0[1], ap0[2], ap0[3], mpos + arow0 + (joff ^ asw0));
            LDSM_X4(ap1[0], ap1[1], ap1[2], ap1[3], mpos + arow1 + (joff ^ asw1));
            LDSM_X4(an0[0], an0[1], an0[2], an0[3], mneg + arow0 + (joff ^ asw0));
            LDSM_X4(an1[0], an1[1], an1[2], an1[3], mneg + arow1 + (joff ^ asw1));

            {
                uint32_t b0[4], b1[4];
                const uint32_t pb = bufb + brow;
                LDSM_X4(b0[0], b0[1], b0[2], b0[3], pb + ((((uint32_t)ks << 5) | 0u)  ^ bsw));
                LDSM_X4(b1[0], b1[1], b1[2], b1[3], pb + ((((uint32_t)ks << 5) | 16u) ^ bsw));
#pragma unroll
                for (int nt = 0; nt < 4; nt++) {
                    MMA16816(dp[0][nt], ap0[0], ap0[1], ap0[2], ap0[3], b0[nt], b1[nt]);
                    MMA16816(dp[1][nt], ap1[0], ap1[1], ap1[2], ap1[3], b0[nt], b1[nt]);
                }
            }
            {
                uint32_t b0[4], b1[4];
                const uint32_t pb = bufb + BTILE + brow;
                LDSM_X4(b0[0], b0[1], b0[2], b0[3], pb + ((((uint32_t)ks << 5) | 0u)  ^ bsw));
                LDSM_X4(b1[0], b1[1], b1[2], b1[3], pb + ((((uint32_t)ks << 5) | 16u) ^ bsw));
#pragma unroll
                for (int nt = 0; nt < 4; nt++) {
                    MMA16816(dn[0][nt], an0[0], an0[1], an0[2], an0[3], b0[nt], b1[nt]);
                    MMA16816(dn[1][nt], an1[0], an1[1], an1[2], an1[3], b0[nt], b1[nt]);
                }
            }
            // ---- Z-stream MMAs: executed by the 4 warps with warp_n == ks (perfect balance) ----
            if (warp_n == ks) {
                const uint32_t zk = ((uint32_t)ks << 5) + zkb;
                const uint32_t a0 = bufb + zrow + (zk ^ zsw);
                const uint32_t a1 = bufb + zrow + ((zk + 16u) ^ zsw);
                uint32_t bz0, bz1;
                asm volatile("ld.shared.b32 %0, [%1];" : "=r"(bz0) : "r"(a0));
                asm volatile("ld.shared.b32 %0, [%1];" : "=r"(bz1) : "r"(a1));
                MMA16816(dzp[0], ap0[0], ap0[1], ap0[2], ap0[3], bz0, bz1);
                MMA16816(dzp[1], ap1[0], ap1[1], ap1[2], ap1[3], bz0, bz1);
                MMA16816(dzn[0], an0[0], an0[1], an0[2], an0[3], bz0, bz1);
                MMA16816(dzn[1], an1[0], an1[1], an1[2], an1[3], bz0, bz1);
            }
        }

        if (t < 63) build_masks(t + 1, (t + 1) & 1);
        if (t + 2 < 64) {
            prefetch_B(t + 2);
            if (t + 3 < 64) prefetch_bits(t + 3);
        }
        CP_COMMIT();
    }

    // ---- write raw partials ----
    float* pdst = g_pp + (size_t)hh * (NROWS * NOUT);
    float* ndst = g_pn + (size_t)hh * (NROWS * NOUT);
#pragma unroll
    for (int mt = 0; mt < 2; mt++) {
        const int r0 = i0 + ib + mt * 16 + (lane >> 2);
        const int r1 = r0 + 8;
#pragma unroll
        for (int nt = 0; nt < 4; nt++) {
            const int c = cb + nt * 8 + ((lane & 3) << 1);
            *(float2*)&pdst[(size_t)r0 * NOUT + c] = make_float2(dp[mt][nt][0], dp[mt][nt][1]);
            *(float2*)&pdst[(size_t)r1 * NOUT + c] = make_float2(dp[mt][nt][2], dp[mt][nt][3]);
            *(float2*)&ndst[(size_t)r0 * NOUT + c] = make_float2(dn[mt][nt][0], dn[mt][nt][1]);
            *(float2*)&ndst[(size_t)r1 * NOUT + c] = make_float2(dn[mt][nt][2], dn[mt][nt][3]);
        }
    }

    // ---- Z reduction across the 4 ks-slices (reuse dyn as scratch) ----
    __syncthreads();                              // main loop done; dyn free
    {
        float* zred = (float*)dyn;                // [4 ks][128 rows][2 {u,v}]
        if ((lane & 3) == 0) {
            const int g = lane >> 2;
#pragma unroll
            for (int mt = 0; mt < 2; mt++) {
                int r = ib + mt * 16 + g;
                zred[(warp_n * 128 + r) * 2 + 0]       = dzp[mt][0];
                zred[(warp_n * 128 + r + 8) * 2 + 0]   = dzp[mt][2];
                zred[(warp_n * 128 + r) * 2 + 1]       = dzn[mt][1];
                zred[(warp_n * 128 + r + 8) * 2 + 1]   = dzn[mt][3];
            }
        }
        __syncthreads();
        if (tid < 128) {
            float zu = 0.f, zv = 0.f;
#pragma unroll
            for (int k = 0; k < 4; k++) {
                zu += zred[(k * 128 + tid) * 2 + 0];
                zv += zred[(k * 128 + tid) * 2 + 1];
            }
            g_zu[hh * NROWS + i0 + tid] = zu;
            g_zv[hh * NROWS + i0 + tid] = zv;
        }
    }

    // ---- device-wide barrier (grid=128, 1 CTA/SM: all resident) ----
    __threadfence();
    __syncthreads();
    if (tid == 0) {
        unsigned t0 = atomicAdd(&g_cnt, 1u);
        unsigned target = ((t0 >> 7) + 1u) << 7;
        unsigned cur;
        do {
            asm volatile("ld.acquire.gpu.u32 %0, [%1];" : "=r"(cur) : "l"(&g_cnt));
            if (cur < target) __nanosleep(128);
        } while (cur < target);
    }
    __syncthreads();

    // ---- combine ----
    {
        const int rbase = blockIdx.x * 64;
#pragma unroll
        for (int it = 0; it < 4; it++) {
            int u = tid + it * 512;
            int r = rbase + (u >> 5);
            int c = (u & 31) * 4;
            float A = g_A[r], Cc = g_C[r];
            float z = A * (g_zu[r] + g_zu[NROWS + r]) + Cc * (g_zv[r] + g_zv[NROWS + r]);
            float zi = 1.f / z;
            const float4 p0 = *(const float4*)&g_pp[(size_t)r * NOUT + c];
            const float4 p1 = *(const float4*)&g_pp[(size_t)(NROWS + r) * NOUT + c];
            const float4 n0 = *(const float4*)&g_pn[(size_t)r * NOUT + c];
            const float4 n1 = *(const float4*)&g_pn[(size_t)(NROWS + r) * NOUT + c];
            float4 o;
            o.x = (A * (p0.x + p1.x) + Cc * (n0.x + n1.x)) * zi;
            o.y = (A * (p0.y + p1.y) + Cc * (n0.y + n1.y)) * zi;
            o.z = (A * (p0.z + p1.z) + Cc * (n0.z + n1.z)) * zi;
            o.w = (A * (p0.w + p1.w) + Cc * (n0.w + n1.w)) * zi;
            *(float4*)&out[(size_t)r * NOUT + c] = o;
        }
    }
}

// ---------------- launcher ----------------
extern "C" void kernel_launch(void* const* d_in, const int* in_sizes, int n_in,
                              void* d_out, int out_size) {
    const float* h = nullptr; const int* adj = nullptr; const float* W = nullptr; const float* a = nullptr;
    for (int k = 0; k < n_in; k++) {
        switch (in_sizes[k]) {
            case NROWS * INP:   h   = (const float*)d_in[k]; break;
            case NROWS * NROWS: adj = (const int*)d_in[k];   break;
            case INP * NOUT:    W   = (const float*)d_in[k]; break;
            case 2 * NOUT:      a   = (const float*)d_in[k]; break;
            default: break;
        }
    }
    float* out = (float*)d_out;

    cudaFuncSetAttribute(k4_hmma, cudaFuncAttributeMaxDynamicSharedMemorySize, DYNSMEM);

    kA     <<<128 + NROWS, 256>>>(h, W, a, adj);
    k4_hmma<<<128, 512, DYNSMEM>>>(out);
}

// round 14
// speedup vs baseline: 1.2798x; 1.0266x over previous
#include <cuda_runtime.h>
#include <cuda_fp16.h>
#include <stdint.h>

#define NROWS 8192
#define INP   512
#define NOUT  128
#define SLOPE 0.2f

// ---------------- device scratch ----------------
__device__ float  g_f1[NROWS];
__device__ float  g_f2[NROWS];
__device__ float  g_A[NROWS];
__device__ float  g_C[NROWS];
__device__ unsigned int g_bits[NROWS * 256];    // 8 MB bitpacked adj
__device__ uint4  g_UVT2[2 * 128 * 1024];       // 4 MB: {U,V} fp16 pre-swizzled B^T tiles
__device__ uint4  g_ZT[128 * 64];               // per chunk: 8 rows x 64 j fp16 (u, v, zero...)
__device__ float  g_pp[2 * NROWS * NOUT];
__device__ float  g_pn[2 * NROWS * NOUT];
__device__ float  g_zu[2 * NROWS];
__device__ float  g_zv[2 * NROWS];
__device__ unsigned int g_cnt;

// ---------------- helpers ----------------
__device__ __forceinline__ uint32_t smem_u32(const void* p) {
    uint32_t r;
    asm("{ .reg .u64 t; cvta.to.shared.u64 t, %1; cvt.u32.u64 %0, t; }" : "=r"(r) : "l"(p));
    return r;
}
#define SW128(x) ((x) ^ (((x) >> 3) & 0x70))

#define LDSM_X4(r0, r1, r2, r3, addr) \
    asm volatile("ldmatrix.sync.aligned.m8n8.x4.shared.b16 {%0,%1,%2,%3}, [%4];" \
        : "=r"(r0), "=r"(r1), "=r"(r2), "=r"(r3) : "r"(addr))

#define MMA16816(d, a0, a1, a2, a3, b0, b1) \
    asm volatile("mma.sync.aligned.m16n8k16.row.col.f32.f16.f16.f32 " \
        "{%0,%1,%2,%3},{%4,%5,%6,%7},{%8,%9},{%0,%1,%2,%3};" \
        : "+f"((d)[0]), "+f"((d)[1]), "+f"((d)[2]), "+f"((d)[3]) \
        : "r"(a0), "r"(a1), "r"(a2), "r"(a3), "r"(b0), "r"(b1))

__device__ __forceinline__ void cp_async16(uint32_t dst, const void* src) {
    asm volatile("cp.async.cg.shared.global [%0], [%1], 16;" :: "r"(dst), "l"(src) : "memory");
}
__device__ __forceinline__ void cp_async8(uint32_t dst, const void* src) {
    asm volatile("cp.async.ca.shared.global [%0], [%1], 8;" :: "r"(dst), "l"(src) : "memory");
}
#define CP_COMMIT() asm volatile("cp.async.commit_group;" ::: "memory")
#define CP_WAIT1()  asm volatile("cp.async.wait_group 1;" ::: "memory")

__device__ __forceinline__ unsigned pack_f16x2(float lo, float hi) {
    unsigned r;
    asm("cvt.rn.f16x2.f32 %0, %1, %2;" : "=r"(r) : "f"(hi), "f"(lo));
    return r;
}
__device__ __forceinline__ unsigned dup_f16(float f) {
    unsigned r;
    asm("{ .reg .f16 h; cvt.rn.f16.f32 h, %1; mov.b32 %0, {h, h}; }" : "=r"(r) : "f"(f));
    return r;
}

// ============ kA: [Wh GEMM + features + UVT/ZT] blocks + adj bitpack blocks (R8 layout) ============
__global__ __launch_bounds__(256) void kA(const float* __restrict__ h, const float* __restrict__ W,
                                          const float* __restrict__ a, const int* __restrict__ adj) {
    if (blockIdx.x >= 128) {
        const int i = blockIdx.x - 128;
        const int w = threadIdx.x >> 5, lane = threadIdx.x & 31;
        const int* row = adj + (size_t)i * NROWS;
#pragma unroll
        for (int q = 0; q < 32; q++) {
            int widx = w + q * 8;
            int v = row[widx * 32 + lane];
            unsigned m = __ballot_sync(0xffffffffu, v != 0);
            if (lane == 0) g_bits[(size_t)i * 256 + widx] = m;
        }
        return;
    }

    __shared__ float hs[64][33];
    __shared__ float Ws[32][128];
    const int t  = threadIdx.x;
    const int i0 = blockIdx.x * 64;
    const int tx = t & 31;
    const int ty = t >> 5;

    float acc[8][4];
#pragma unroll
    for (int r = 0; r < 8; r++)
#pragma unroll
        for (int c = 0; c < 4; c++) acc[r][c] = 0.f;

    for (int k0 = 0; k0 < INP; k0 += 32) {
#pragma unroll
        for (int p = 0; p < 2; p++) {
            int u = t + p * 256;
            int r = u >> 3, kc = (u & 7) * 4;
            float4 hv = *(const float4*)(h + (size_t)(i0 + r) * INP + k0 + kc);
            hs[r][kc] = hv.x; hs[r][kc + 1] = hv.y; hs[r][kc + 2] = hv.z; hs[r][kc + 3] = hv.w;
        }
#pragma unroll
        for (int p = 0; p < 4; p++) {
            int u = t + p * 256;
            int kr = u >> 5, cc = (u & 31) * 4;
            *(float4*)&Ws[kr][cc] = *(const float4*)(W + (size_t)(k0 + kr) * NOUT + cc);
        }
        __syncthreads();
#pragma unroll
        for (int kk = 0; kk < 32; kk++) {
            float4 bv = *(float4*)&Ws[kk][tx * 4];
#pragma unroll
            for (int r = 0; r < 8; r++) {
                float av = hs[ty * 8 + r][kk];
                acc[r][0] += av * bv.x; acc[r][1] += av * bv.y;
                acc[r][2] += av * bv.z; acc[r][3] += av * bv.w;
            }
        }
        __syncthreads();
    }

    float4 a1 = __ldg((const float4*)(a + tx * 4));
    float4 a2 = __ldg((const float4*)(a + 128 + tx * 4));
    float uu[8], vv[8];
#pragma unroll
    for (int r = 0; r < 8; r++) {
        float s1 = acc[r][0] * a1.x + acc[r][1] * a1.y + acc[r][2] * a1.z + acc[r][3] * a1.w;
        float s2 = acc[r][0] * a2.x + acc[r][1] * a2.y + acc[r][2] * a2.z + acc[r][3] * a2.w;
#pragma unroll
        for (int off = 16; off > 0; off >>= 1) {
            s1 += __shfl_xor_sync(0xffffffffu, s1, off);
            s2 += __shfl_xor_sync(0xffffffffu, s2, off);
        }
        uu[r] = expf(s2);
        vv[r] = expf(SLOPE * s2);
        if (tx == r) {
            int j = i0 + ty * 8 + r;
            g_f1[j] = s1;
            g_f2[j] = s2;
            g_A[j]  = expf(s1);
            g_C[j]  = expf(SLOPE * s1);
        }
    }

    const int jbase = ty * 8;
    char* base = (char*)g_UVT2 + (size_t)blockIdx.x * 16384;
#pragma unroll
    for (int rp = 0; rp < 4; rp++) {
#pragma unroll
        for (int c = 0; c < 4; c++) {
            float U0 = uu[2 * rp] * acc[2 * rp][c],     U1 = uu[2 * rp + 1] * acc[2 * rp + 1][c];
            float V0 = vv[2 * rp] * acc[2 * rp][c],     V1 = vv[2 * rp + 1] * acc[2 * rp + 1][c];
            unsigned off = SW128((unsigned)((tx * 4 + c) * 128 + (jbase + 2 * rp) * 2));
            *(unsigned*)(base + off)            = pack_f16x2(U0, U1);
            *(unsigned*)(base + 2097152u + off) = pack_f16x2(V0, V1);
        }
    }

    {
        char* zb = (char*)g_ZT + (size_t)blockIdx.x * 1024;
        int rsel = tx & 7;
        float us = uu[0], vs = vv[0];
#pragma unroll
        for (int r = 1; r < 8; r++) if (rsel == r) { us = uu[r]; vs = vv[r]; }
        int n = tx >> 3;
        if (n < 2) {
            float val = (n == 0) ? us : vs;
            unsigned off = (unsigned)(n * 128) + (((unsigned)((jbase + rsel) * 2)) ^ ((unsigned)n << 4));
            *(__half*)(zb + off) = __float2half(val);
        }
        if (t < 192) {
            int zn = 2 + (t >> 5);
            unsigned zoff = (unsigned)(zn * 128) + ((((unsigned)(t & 31)) * 4u) ^ ((unsigned)(zn & 7) << 4));
            *(unsigned*)(zb + zoff) = 0u;
        }
    }
}

// ============ K4: 2 CTAs/SM, 64 rows each, fp16 HMMA masked GEMMs ============
#define MASKBUF   16384                          // pos 8K + neg 8K (64 rows)
#define BTILE     16384
#define ZTB       1024
#define BBUF      (2 * BTILE + ZTB)              // 33792
#define DYNSMEM   (2 * MASKBUF + 2 * BBUF)       // 100352

__global__ void __launch_bounds__(256, 2) k4_hmma(float* __restrict__ out) {
    extern __shared__ __align__(16) char dyn[];
    __shared__ float  s_f1[64];
    __shared__ __align__(16) __half s_f2h[4096];
    __shared__ __align__(16) unsigned sbits[3 * 128];   // 3 slots x (64 rows x 2 words)

    const int tid  = threadIdx.x;
    const int wid  = tid >> 5;
    const int lane = tid & 31;
    const int rt = blockIdx.x >> 1;       // 128 row-tiles of 64
    const int hh = blockIdx.x & 1;
    const int i0 = rt << 6;
    const int j0 = hh << 12;

    const uint32_t dbase  = smem_u32(dyn);
    const uint32_t bbuf_u = dbase + 2u * MASKBUF;
    const uint32_t sbits_u = smem_u32(sbits);

    if (tid < 64) s_f1[tid] = g_f1[i0 + tid];
    for (int q = tid; q < 4096; q += 256) s_f2h[q] = __float2half(g_f2[j0 + q]);
    __syncthreads();

    float dp[2][4][4], dn[2][4][4];
    float dzp[2][4], dzn[2][4];
#pragma unroll
    for (int mt = 0; mt < 2; mt++) {
#pragma unroll
        for (int nt = 0; nt < 4; nt++)
#pragma unroll
            for (int r = 0; r < 4; r++) { dp[mt][nt][r] = 0.f; dn[mt][nt][r] = 0.f; }
#pragma unroll
        for (int r = 0; r < 4; r++) { dzp[mt][r] = 0.f; dzn[mt][r] = 0.f; }
    }

    const int warp_m = wid >> 2;          // 0..1 (32 rows each)
    const int warp_n = wid & 3;
    const int ib = warp_m << 5;
    const int cb = warp_n << 5;

    const int ri0 = ib + (lane & 15);
    const int ri1 = ri0 + 16;
    const uint32_t arow0 = (uint32_t)ri0 * 128u, asw0 = (uint32_t)(ri0 & 7) << 4;
    const uint32_t arow1 = (uint32_t)ri1 * 128u, asw1 = (uint32_t)(ri1 & 7) << 4;
    const uint32_t akh   = (uint32_t)(lane >> 4) << 4;
    const int cr = cb + lane;
    const uint32_t brow = (uint32_t)cr * 128u, bsw = (uint32_t)(cr & 7) << 4;

    const uint32_t zn   = (uint32_t)(lane >> 2);
    const uint32_t zsw  = (zn & 7u) << 4;
    const uint32_t zrow = 2u * BTILE + zn * 128u;
    const uint32_t zkb  = ((uint32_t)(lane & 3)) << 2;

    auto prefetch_bits = [&](int c) {
        if (tid < 64) {
            uint32_t dst = sbits_u + (uint32_t)(c % 3) * 512u + (uint32_t)tid * 8u;
            const unsigned* src = &g_bits[(size_t)(i0 + tid) * 256 + (unsigned)((j0 + (c << 6)) >> 5)];
            cp_async8(dst, src);
        }
    };

    // mask build: f16x2 math, 2 units x 8 j per thread (64 rows x 64 j)
    auto build_masks = [&](int c, int mb) {
        char* mdst = dyn + mb * MASKBUF;
        const int tch = c << 6;
        const unsigned* sb = sbits + (c % 3) * 128;
#pragma unroll
        for (int un = 0; un < 2; un++) {
            const int unit = (tid << 1) | un;
            const int i  = unit >> 3;            // 0..63
            const int jl = (unit & 7) << 3;      // 0..56
            const unsigned word = sb[i * 2 + (jl >> 5)];
            const unsigned bits8 = (word >> (jl & 31)) & 0xFFu;
            const unsigned thr2 = dup_f16(-s_f1[i]);
            uint4 wp4, wn4;
            unsigned* wp = (unsigned*)&wp4;
            unsigned* wn = (unsigned*)&wn4;
#pragma unroll
            for (int p = 0; p < 4; p++) {
                unsigned f2h2 = *(const unsigned*)&s_f2h[tch + jl + p * 2];
                unsigned x = (bits8 >> (p * 2)) & 3u;
                unsigned b2 = (x & 1u) * 0x3C00u + (x >> 1) * 0x3C000000u;
                unsigned s2, pos, neg;
                asm("set.ge.f16x2.f16x2 %0, %1, %2;" : "=r"(s2) : "r"(f2h2), "r"(thr2));
                asm("mul.rn.f16x2 %0, %1, %2;" : "=r"(pos) : "r"(b2), "r"(s2));
                asm("sub.rn.f16x2 %0, %1, %2;" : "=r"(neg) : "r"(b2), "r"(pos));
                wp[p] = pos;
                wn[p] = neg;
            }
            const uint32_t off = (uint32_t)i * 128u + (((uint32_t)(jl << 1)) ^ ((uint32_t)(i & 7) << 4));
            *(uint4*)(mdst + off)         = wp4;
            *(uint4*)(mdst + 8192 + off)  = wn4;
        }
    };

    auto prefetch_B = [&](int c) {
        const int nc = (hh << 6) + c;
        const uint32_t dstb = bbuf_u + (uint32_t)(c & 1) * BBUF;
        const char* srcb = (const char*)g_UVT2 + (size_t)nc * 16384;
#pragma unroll
        for (int pass = 0; pass < 8; pass++) {
            int u = tid + pass * 256;
            int m = u >> 10;
            uint32_t off = (uint32_t)(u & 1023) << 4;
            cp_async16(dstb + (uint32_t)m * BTILE + off, srcb + (size_t)m * 2097152 + off);
        }
        if (tid < 64)
            cp_async16(dstb + 2u * BTILE + (uint32_t)tid * 16u,
                       (const char*)g_ZT + (size_t)nc * 1024 + tid * 16);
    };

    // ---- prologue ----
    prefetch_bits(0);
    prefetch_bits(1);
    prefetch_B(0);
    CP_COMMIT();                 // g0: B0, bits0, bits1
    prefetch_bits(2);
    prefetch_B(1);
    CP_COMMIT();                 // g1: B1, bits2
    CP_WAIT1();                  // g0 done
    __syncthreads();
    build_masks(0, 0);

    for (int t = 0; t < 64; t++) {
        CP_WAIT1();              // B[t] + bits up to t+2 done (newest group outstanding)
        __syncthreads();         // sync#1: masks[t] + B[t] visible

        const uint32_t mpos = dbase + (uint32_t)(t & 1) * MASKBUF;
        const uint32_t mneg = mpos + 8192u;
        const uint32_t bufb = bbuf_u + (uint32_t)(t & 1) * BBUF;

#pragma unroll
        for (int ks = 0; ks < 4; ks++) {
            const uint32_t joff = ((uint32_t)ks << 5) | akh;
            uint32_t ap0[4], ap1[4], an0[4], an1[4];
            LDSM_X4(ap0[0], ap0[1], ap0[2], ap0[3], mpos + arow0 + (joff ^ asw0));
            LDSM_X4(ap1[0], ap1[1], ap1[2], ap1[3], mpos + arow1 + (joff ^ asw1));
            LDSM_X4(an0[0], an0[1], an0[2], an0[3], mneg + arow0 + (joff ^ asw0));
            LDSM_X4(an1[0], an1[1], an1[2], an1[3], mneg + arow1 + (joff ^ asw1));

            {
                uint32_t b0[4], b1[4];
                const uint32_t pb = bufb + brow;
                LDSM_X4(b0[0], b0[1], b0[2], b0[3], pb + ((((uint32_t)ks << 5) | 0u)  ^ bsw));
                LDSM_X4(b1[0], b1[1], b1[2], b1[3], pb + ((((uint32_t)ks << 5) | 16u) ^ bsw));
#pragma unroll
                for (int nt = 0; nt < 4; nt++) {
                    MMA16816(dp[0][nt], ap0[0], ap0[1], ap0[2], ap0[3], b0[nt], b1[nt]);
                    MMA16816(dp[1][nt], ap1[0], ap1[1], ap1[2], ap1[3], b0[nt], b1[nt]);
                }
            }
            {
                uint32_t b0[4], b1[4];
                const uint32_t pb = bufb + BTILE + brow;
                LDSM_X4(b0[0], b0[1], b0[2], b0[3], pb + ((((uint32_t)ks << 5) | 0u)  ^ bsw));
                LDSM_X4(b1[0], b1[1], b1[2], b1[3], pb + ((((uint32_t)ks << 5) | 16u) ^ bsw));
#pragma unroll
                for (int nt = 0; nt < 4; nt++) {
                    MMA16816(dn[0][nt], an0[0], an0[1], an0[2], an0[3], b0[nt], b1[nt]);
                    MMA16816(dn[1][nt], an1[0], an1[1], an1[2], an1[3], b0[nt], b1[nt]);
                }
            }
            if (warp_n == ks) {
                const uint32_t zk = ((uint32_t)ks << 5) + zkb;
                const uint32_t a0 = bufb + zrow + (zk ^ zsw);
                const uint32_t a1 = bufb + zrow + ((zk + 16u) ^ zsw);
                uint32_t bz0, bz1;
                asm volatile("ld.shared.b32 %0, [%1];" : "=r"(bz0) : "r"(a0));
                asm volatile("ld.shared.b32 %0, [%1];" : "=r"(bz1) : "r"(a1));
                MMA16816(dzp[0], ap0[0], ap0[1], ap0[2], ap0[3], bz0, bz1);
                MMA16816(dzp[1], ap1[0], ap1[1], ap1[2], ap1[3], bz0, bz1);
                MMA16816(dzn[0], an0[0], an0[1], an0[2], an0[3], bz0, bz1);
                MMA16816(dzn[1], an1[0], an1[1], an1[2], an1[3], bz0, bz1);
            }
        }

        if (t < 63) build_masks(t + 1, (t + 1) & 1);   // reads sbits slot (t+1)%3; writes mask buf read at t-1
        __syncthreads();          // sync#2: all warps done reading B buf t&1 / sbits slot t%3
        if (t + 2 < 64) prefetch_B(t + 2);             // into buf t&1 (safe post-sync)
        if (t + 3 < 64) prefetch_bits(t + 3);          // slot t%3 (read finished at build(t), pre-sync)
        CP_COMMIT();
    }

    // ---- write raw partials ----
    float* pdst = g_pp + (size_t)hh * (NROWS * NOUT);
    float* ndst = g_pn + (size_t)hh * (NROWS * NOUT);
#pragma unroll
    for (int mt = 0; mt < 2; mt++) {
        const int r0 = i0 + ib + mt * 16 + (lane >> 2);
        const int r1 = r0 + 8;
#pragma unroll
        for (int nt = 0; nt < 4; nt++) {
            const int c = cb + nt * 8 + ((lane & 3) << 1);
            *(float2*)&pdst[(size_t)r0 * NOUT + c] = make_float2(dp[mt][nt][0], dp[mt][nt][1]);
            *(float2*)&pdst[(size_t)r1 * NOUT + c] = make_float2(dp[mt][nt][2], dp[mt][nt][3]);
            *(float2*)&ndst[(size_t)r0 * NOUT + c] = make_float2(dn[mt][nt][0], dn[mt][nt][1]);
            *(float2*)&ndst[(size_t)r1 * NOUT + c] = make_float2(dn[mt][nt][2], dn[mt][nt][3]);
        }
    }

    // ---- Z reduction across the 4 ks-slices (reuse dyn as scratch) ----
    __syncthreads();
    {
        float* zred = (float*)dyn;                // [4 ks][64 rows][2 {u,v}]
        if ((lane & 3) == 0) {
            const int g = lane >> 2;
#pragma unroll
            for (int mt = 0; mt < 2; mt++) {
                int r = ib + mt * 16 + g;
                zred[(warp_n * 64 + r) * 2 + 0]       = dzp[mt][0];
                zred[(warp_n * 64 + r + 8) * 2 + 0]   = dzp[mt][2];
                zred[(warp_n * 64 + r) * 2 + 1]       = dzn[mt][1];
                zred[(warp_n * 64 + r + 8) * 2 + 1]   = dzn[mt][3];
            }
        }
        __syncthreads();
        if (tid < 64) {
            float zu = 0.f, zv = 0.f;
#pragma unroll
            for (int k = 0; k < 4; k++) {
                zu += zred[(k * 64 + tid) * 2 + 0];
                zv += zred[(k * 64 + tid) * 2 + 1];
            }
            g_zu[hh * NROWS + i0 + tid] = zu;
            g_zv[hh * NROWS + i0 + tid] = zv;
        }
    }

    // ---- device-wide barrier (grid=256, all resident at 2 CTA/SM) ----
    __threadfence();
    __syncthreads();
    if (tid == 0) {
        unsigned t0 = atomicAdd(&g_cnt, 1u);
        unsigned target = ((t0 >> 8) + 1u) << 8;
        unsigned cur;
        do {
            asm volatile("ld.acquire.gpu.u32 %0, [%1];" : "=r"(cur) : "l"(&g_cnt));
            if (cur < target) __nanosleep(128);
        } while (cur < target);
    }
    __syncthreads();

    // ---- combine: this CTA normalizes rows [bid*32, bid*32+32) ----
    {
        const int rbase = blockIdx.x * 32;
#pragma unroll
        for (int it = 0; it < 4; it++) {
            int u = tid + it * 256;
            int r = rbase + (u >> 5);
            int c = (u & 31) * 4;
            float A = g_A[r], Cc = g_C[r];
            float z = A * (g_zu[r] + g_zu[NROWS + r]) + Cc * (g_zv[r] + g_zv[NROWS + r]);
            float zi = 1.f / z;
            const float4 p0 = *(const float4*)&g_pp[(size_t)r * NOUT + c];
            const float4 p1 = *(const float4*)&g_pp[(size_t)(NROWS + r) * NOUT + c];
            const float4 n0 = *(const float4*)&g_pn[(size_t)r * NOUT + c];
            const float4 n1 = *(const float4*)&g_pn[(size_t)(NROWS + r) * NOUT + c];
            float4 o;
            o.x = (A * (p0.x + p1.x) + Cc * (n0.x + n1.x)) * zi;
            o.y = (A * (p0.y + p1.y) + Cc * (n0.y + n1.y)) * zi;
            o.z = (A * (p0.z + p1.z) + Cc * (n0.z + n1.z)) * zi;
            o.w = (A * (p0.w + p1.w) + Cc * (n0.w + n1.w)) * zi;
            *(float4*)&out[(size_t)r * NOUT + c] = o;
        }
    }
}

// ---------------- launcher ----------------
extern "C" void kernel_launch(void* const* d_in, const int* in_sizes, int n_in,
                              void* d_out, int out_size) {
    const float* h = nullptr; const int* adj = nullptr; const float* W = nullptr; const float* a = nullptr;
    for (int k = 0; k < n_in; k++) {
        switch (in_sizes[k]) {
            case NROWS * INP:   h   = (const float*)d_in[k]; break;
            case NROWS * NROWS: adj = (const int*)d_in[k];   break;
            case INP * NOUT:    W   = (const float*)d_in[k]; break;
            case 2 * NOUT:      a   = (const float*)d_in[k]; break;
            default: break;
        }
    }
    float* out = (float*)d_out;

    cudaFuncSetAttribute(k4_hmma, cudaFuncAttributeMaxDynamicSharedMemorySize, DYNSMEM);

    kA     <<<128 + NROWS, 256>>>(h, W, a, adj);
    k4_hmma<<<256, 256, DYNSMEM>>>(out);
}